// round 7
// baseline (speedup 1.0000x reference)
#include <cuda_runtime.h>
#include <cstdint>
#include <math.h>

#define Nb 2
#define T  2048
#define H  256
#define NH 8
#define D  32
#define SCALE 17.677669529663689f

typedef unsigned long long u64;
typedef uint32_t u32;

__device__ __forceinline__ void fma2(u64& d, u64 a, u64 b) {
    asm("fma.rn.f32x2 %0, %1, %2, %0;" : "+l"(d) : "l"(a), "l"(b));
}
__device__ __forceinline__ u64 pack2(float x, float y) {
    u64 r; asm("mov.b64 %0, {%1, %2};" : "=l"(r) : "f"(x), "f"(y)); return r;
}
__device__ __forceinline__ float2 unpack2(u64 v) {
    float2 f; asm("mov.b64 {%0, %1}, %2;" : "=f"(f.x), "=f"(f.y) : "l"(v)); return f;
}
__device__ __forceinline__ u32 tf32_hi(float x) {
    u32 h; asm("cvt.rna.tf32.f32 %0, %1;" : "=r"(h) : "f"(x)); return h;
}
__device__ __forceinline__ void tf32_split(float x, u32& hi, u32& lo) {
    hi = tf32_hi(x);
    lo = tf32_hi(x - __uint_as_float(hi));
}
#define MMA(c, a, b0, b1) \
    asm volatile("mma.sync.aligned.m16n8k8.row.col.f32.tf32.tf32.f32 " \
        "{%0,%1,%2,%3}, {%4,%5,%6,%7}, {%8,%9}, {%0,%1,%2,%3};" \
        : "+f"((c)[0]), "+f"((c)[1]), "+f"((c)[2]), "+f"((c)[3]) \
        : "r"((a)[0]), "r"((a)[1]), "r"((a)[2]), "r"((a)[3]), "r"(b0), "r"(b1))

__device__ __align__(16) float g_Qh[Nb*NH*T*D];
__device__ __align__(16) float g_Kh[Nb*NH*T*D];
__device__ __align__(16) float g_Vh[Nb*NH*T*D];
__device__ __align__(16) float g_ctx[Nb*T*H];
__device__ float g_kbias[Nb*T];   /* 0 or -1e35 */
__device__ float g_qmask[Nb*T];

/* ------------------------------------------------------------------ */
__global__ void mask_kernel(const float* __restrict__ Q,
                            const float* __restrict__ K) {
    int row = blockIdx.x;
    const float* src = blockIdx.y ? K : Q;
    int t = threadIdx.x;
    float s = fabsf(src[row*H + t]) + fabsf(src[row*H + t + 128]);
    __shared__ float red[4];
    #pragma unroll
    for (int o = 16; o; o >>= 1) s += __shfl_xor_sync(0xffffffffu, s, o);
    if ((t & 31) == 0) red[t >> 5] = s;
    __syncthreads();
    if (t == 0) {
        float tot = red[0] + red[1] + red[2] + red[3];
        if (blockIdx.y) g_kbias[row] = (tot != 0.0f) ? 0.0f : -1e35f;
        else            g_qmask[row] = (tot != 0.0f) ? 1.0f : 0.0f;
    }
}

/* ------------------------------------------------------------------ */
__global__ void __launch_bounds__(256) proj_kernel(
        const float* __restrict__ Q, const float* __restrict__ K,
        const float* __restrict__ V,
        const float* __restrict__ Wq, const float* __restrict__ Wk,
        const float* __restrict__ Wv,
        const float* __restrict__ bq, const float* __restrict__ bk,
        const float* __restrict__ bv) {
    int sel = blockIdx.z;
    const float* X = (sel == 0) ? Q  : (sel == 1) ? K  : V;
    const float* W = (sel == 0) ? Wq : (sel == 1) ? Wk : Wv;
    const float* b = (sel == 0) ? bq : (sel == 1) ? bk : bv;
    float* dst     = (sel == 0) ? g_Qh : (sel == 1) ? g_Kh : g_Vh;
    int m0 = blockIdx.y * 64, n0 = blockIdx.x * 64;
    __shared__ __align__(16) float Xst[32][68];
    __shared__ __align__(16) float Wsh[32][68];
    int tid = threadIdx.x, ty = tid >> 4, tx = tid & 15;
    u64 acc2[4][2] = {};
    for (int k0 = 0; k0 < H; k0 += 32) {
        __syncthreads();
        #pragma unroll
        for (int it = 0; it < 8; ++it) {
            int e = tid + it * 256;
            int r = e >> 5, c = e & 31;
            Xst[c][r] = X[(m0 + r) * H + k0 + c];
            int r2 = e >> 6, c2 = e & 63;
            Wsh[r2][c2] = W[(k0 + r2) * H + n0 + c2];
        }
        __syncthreads();
        #pragma unroll
        for (int kk = 0; kk < 32; ++kk) {
            float4 a = *(const float4*)&Xst[kk][4 * ty];
            ulonglong2 bb = *(const ulonglong2*)&Wsh[kk][4 * tx];
            u64 a0 = pack2(a.x, a.x), a1 = pack2(a.y, a.y);
            u64 a2 = pack2(a.z, a.z), a3 = pack2(a.w, a.w);
            fma2(acc2[0][0], a0, bb.x); fma2(acc2[0][1], a0, bb.y);
            fma2(acc2[1][0], a1, bb.x); fma2(acc2[1][1], a1, bb.y);
            fma2(acc2[2][0], a2, bb.x); fma2(acc2[2][1], a2, bb.y);
            fma2(acc2[3][0], a3, bb.x); fma2(acc2[3][1], a3, bb.y);
        }
    }
    int c0 = n0 + 4 * tx, hh = c0 >> 5, d0 = c0 & 31;
    float b0 = b[c0+0], b1 = b[c0+1], b2 = b[c0+2], b3 = b[c0+3];
    #pragma unroll
    for (int i = 0; i < 4; ++i) {
        int m = m0 + 4 * ty + i, nn = m >> 11, tt = m & 2047;
        float2 lo = unpack2(acc2[i][0]), hi = unpack2(acc2[i][1]);
        float4 o;
        o.x = fmaxf(lo.x + b0, 0.0f); o.y = fmaxf(lo.y + b1, 0.0f);
        o.z = fmaxf(hi.x + b2, 0.0f); o.w = fmaxf(hi.y + b3, 0.0f);
        *(float4*)&dst[(((nn * NH) + hh) * T + tt) * D + d0] = o;
    }
}

/* ------------------------------------------------------------------ */
/* 3xTF32 mma flash attention. Grid (16, NH, Nb), 256 thr (8 warps).  */
/* Warp owns 16 q-rows (1 m16 frag). K macro-tile 64, halves of 32.   */
#define KPITCH 68
#define VPITCH 36
#define PPITCH 36
#define SM_FLOATS (2*32*KPITCH + 2*64*VPITCH + 8*16*PPITCH + 64)
#define SMEM_BYTES (SM_FLOATS * 4)

__global__ void __launch_bounds__(256, 2) attn_kernel() {
    extern __shared__ __align__(16) float dsm[];
    float* Khi = dsm;                       /* [32][KPITCH] d-major   */
    float* Klo = Khi + 32 * KPITCH;
    float* Vhi = Klo + 32 * KPITCH;         /* [64][VPITCH] key-major */
    float* Vlo = Vhi + 64 * VPITCH;
    float* Ps  = Vlo + 64 * VPITCH;         /* [8][16][PPITCH]        */
    float* bias_s = Ps + 8 * 16 * PPITCH;

    int tid = threadIdx.x, w = tid >> 5, lane = tid & 31;
    int g = lane >> 2, tq = lane & 3;
    int q0 = blockIdx.x * 128, hh = blockIdx.y, nn = blockIdx.z;
    const float* Qg = g_Qh + (size_t)(nn * NH + hh) * T * D;
    const float* Kg = g_Kh + (size_t)(nn * NH + hh) * T * D;
    const float* Vg = g_Vh + (size_t)(nn * NH + hh) * T * D;
    float* Pw = Ps + w * 16 * PPITCH;

    /* Q fragments (loop-invariant): rows q0+16w+g(+8), cols 8ks+tq(+4) */
    u32 qh[4][4], ql[4][4];
    {
        int r0 = (q0 + 16 * w + g) * D;
        int r1 = r0 + 8 * D;
        #pragma unroll
        for (int ks = 0; ks < 4; ++ks) {
            tf32_split(Qg[r0 + 8*ks + tq],     qh[ks][0], ql[ks][0]);
            tf32_split(Qg[r1 + 8*ks + tq],     qh[ks][1], ql[ks][1]);
            tf32_split(Qg[r0 + 8*ks + tq + 4], qh[ks][2], ql[ks][2]);
            tf32_split(Qg[r1 + 8*ks + tq + 4], qh[ks][3], ql[ks][3]);
        }
    }
    float O[4][4];
    #pragma unroll
    for (int nf = 0; nf < 4; ++nf)
        #pragma unroll
        for (int c = 0; c < 4; ++c) O[nf][c] = 0.0f;
    float mrun[2] = {-1e30f, -1e30f};
    float lrun[2] = {0.f, 0.f};

    for (int kt = 0; kt < T / 64; ++kt) {
        int k0 = kt * 64;
        __syncthreads();
        #pragma unroll
        for (int i = 0; i < 8; ++i) {     /* K,V tiles -> hi/lo smem */
            int idx = tid + 256 * i;
            int row = idx >> 5, c = idx & 31;
            u32 hb, lb;
            tf32_split(Kg[(k0 + row) * D + c], hb, lb);
            Khi[c * KPITCH + row] = __uint_as_float(hb);
            Klo[c * KPITCH + row] = __uint_as_float(lb);
            tf32_split(Vg[(k0 + row) * D + c], hb, lb);
            Vhi[row * VPITCH + c] = __uint_as_float(hb);
            Vlo[row * VPITCH + c] = __uint_as_float(lb);
        }
        if (tid < 64) bias_s[tid] = g_kbias[nn * T + k0 + tid];
        __syncthreads();

        #pragma unroll
        for (int h = 0; h < 2; ++h) {
            /* ---- S = Q K^T (3xTF32) ---- */
            float s[4][4];
            #pragma unroll
            for (int j = 0; j < 4; ++j)
                #pragma unroll
                for (int c = 0; c < 4; ++c) s[j][c] = 0.0f;
            #pragma unroll
            for (int ks = 0; ks < 4; ++ks) {
                u32 bh[4][2], bl[4][2];
                #pragma unroll
                for (int j = 0; j < 4; ++j) {
                    int col = 32 * h + 8 * j + g;
                    bh[j][0] = __float_as_uint(Khi[(8*ks + tq)     * KPITCH + col]);
                    bh[j][1] = __float_as_uint(Khi[(8*ks + tq + 4) * KPITCH + col]);
                    bl[j][0] = __float_as_uint(Klo[(8*ks + tq)     * KPITCH + col]);
                    bl[j][1] = __float_as_uint(Klo[(8*ks + tq + 4) * KPITCH + col]);
                }
                #pragma unroll
                for (int j = 0; j < 4; ++j) {
                    MMA(s[j], qh[ks], bh[j][0], bh[j][1]);
                    MMA(s[j], ql[ks], bh[j][0], bh[j][1]);
                    MMA(s[j], qh[ks], bl[j][0], bl[j][1]);
                }
            }

            /* ---- softmax (fragment-resident) ---- */
            float2 bb[4];
            #pragma unroll
            for (int j = 0; j < 4; ++j)
                bb[j] = *(float2*)&bias_s[32 * h + 8 * j + 2 * tq];
            #pragma unroll
            for (int rg = 0; rg < 2; ++rg) {
                float zv[8];
                #pragma unroll
                for (int j = 0; j < 4; ++j) {
                    zv[2*j]   = fmaf(s[j][2*rg],   SCALE, bb[j].x);
                    zv[2*j+1] = fmaf(s[j][2*rg+1], SCALE, bb[j].y);
                }
                float mx = zv[0];
                #pragma unroll
                for (int e = 1; e < 8; ++e) mx = fmaxf(mx, zv[e]);
                mx = fmaxf(mx, __shfl_xor_sync(0xffffffffu, mx, 1));
                mx = fmaxf(mx, __shfl_xor_sync(0xffffffffu, mx, 2));
                float mn = fmaxf(mrun[rg], mx);
                float fr = __expf(mrun[rg] - mn);
                mrun[rg] = mn;
                float sum = 0.0f;
                #pragma unroll
                for (int j = 0; j < 4; ++j) {
                    float p0 = __expf(zv[2*j]   - mn);
                    float p1 = __expf(zv[2*j+1] - mn);
                    sum += p0 + p1;
                    s[j][2*rg] = p0; s[j][2*rg+1] = p1;
                }
                sum += __shfl_xor_sync(0xffffffffu, sum, 1);
                sum += __shfl_xor_sync(0xffffffffu, sum, 2);
                lrun[rg] = lrun[rg] * fr + sum;
                #pragma unroll
                for (int nf = 0; nf < 4; ++nf) {
                    O[nf][2*rg]   *= fr;
                    O[nf][2*rg+1] *= fr;
                }
            }

            /* ---- P -> per-warp smem (zero last key in ctx) ---- */
            __syncwarp();
            int kb = k0 + 32 * h + 2 * tq;
            #pragma unroll
            for (int j = 0; j < 4; ++j) {
                float p1 = s[j][1], p3 = s[j][3];
                if (kb + 8*j + 1 == T - 1) { p1 = 0.0f; p3 = 0.0f; }
                *(float2*)&Pw[(g)     * PPITCH + 8*j + 2*tq] = make_float2(s[j][0], p1);
                *(float2*)&Pw[(8 + g) * PPITCH + 8*j + 2*tq] = make_float2(s[j][2], p3);
            }
            __syncwarp();

            /* ---- O += P V (3xTF32) ---- */
            #pragma unroll
            for (int ks = 0; ks < 4; ++ks) {
                u32 ph[4], pl[4];
                tf32_split(Pw[(g)     * PPITCH + 8*ks + tq],     ph[0], pl[0]);
                tf32_split(Pw[(8 + g) * PPITCH + 8*ks + tq],     ph[1], pl[1]);
                tf32_split(Pw[(g)     * PPITCH + 8*ks + tq + 4], ph[2], pl[2]);
                tf32_split(Pw[(8 + g) * PPITCH + 8*ks + tq + 4], ph[3], pl[3]);
                int krow0 = (32*h + 8*ks + tq) * VPITCH;
                int krow1 = (32*h + 8*ks + tq + 4) * VPITCH;
                #pragma unroll
                for (int nf = 0; nf < 4; ++nf) {
                    u32 vh0 = __float_as_uint(Vhi[krow0 + 8*nf + g]);
                    u32 vh1 = __float_as_uint(Vhi[krow1 + 8*nf + g]);
                    u32 vl0 = __float_as_uint(Vlo[krow0 + 8*nf + g]);
                    u32 vl1 = __float_as_uint(Vlo[krow1 + 8*nf + g]);
                    MMA(O[nf], ph, vh0, vh1);
                    MMA(O[nf], pl, vh0, vh1);
                    MMA(O[nf], ph, vl0, vl1);
                }
            }
        }
    }

    /* ---- epilogue ---- */
    #pragma unroll
    for (int rg = 0; rg < 2; ++rg) {
        int row = q0 + 16 * w + 8 * rg + g;
        float inv = g_qmask[nn * T + row] / lrun[rg];
        float* dst = &g_ctx[(size_t)(nn * T + row) * H + hh * D];
        #pragma unroll
        for (int nf = 0; nf < 4; ++nf)
            *(float2*)&dst[8*nf + 2*tq] =
                make_float2(O[nf][2*rg] * inv, O[nf][2*rg+1] * inv);
    }
}

/* ------------------------------------------------------------------ */
__global__ void __launch_bounds__(256) ln_kernel(
        const float* __restrict__ gamma, const float* __restrict__ beta,
        float* __restrict__ out, float* __restrict__ wout) {
    int row = blockIdx.x, t = threadIdx.x;
    float x = g_ctx[(size_t)row * H + t];
    __shared__ float rs[8], rq[8];
    float s = x, q = x * x;
    #pragma unroll
    for (int o = 16; o; o >>= 1) {
        s += __shfl_xor_sync(0xffffffffu, s, o);
        q += __shfl_xor_sync(0xffffffffu, q, o);
    }
    if ((t & 31) == 0) { rs[t >> 5] = s; rq[t >> 5] = q; }
    __syncthreads();
    float ts = 0.0f, tq = 0.0f;
    #pragma unroll
    for (int i = 0; i < 8; ++i) { ts += rs[i]; tq += rq[i]; }
    float mu = ts * (1.0f / H);
    float var = tq * (1.0f / H) - mu * mu;
    float inv = rsqrtf(var + 1e-5f);
    out[(size_t)row * H + t] = (x - mu) * inv * gamma[t] + beta[t];
    if (t == 0) wout[row] = g_qmask[row] * (1.0f / (float)T);
}

/* ------------------------------------------------------------------ */
extern "C" void kernel_launch(void* const* d_in, const int* in_sizes, int n_in,
                              void* d_out, int out_size) {
    const float* Q  = (const float*)d_in[0];
    const float* K  = (const float*)d_in[1];
    const float* V  = (const float*)d_in[2];
    const float* Wq = (const float*)d_in[3];
    const float* bq = (const float*)d_in[4];
    const float* Wk = (const float*)d_in[5];
    const float* bk = (const float*)d_in[6];
    const float* Wv = (const float*)d_in[7];
    const float* bv = (const float*)d_in[8];
    const float* gamma = (const float*)d_in[9];
    const float* beta  = (const float*)d_in[10];

    float* out  = (float*)d_out;
    float* wout = out + (out_size - Nb * T);

    cudaFuncSetAttribute(attn_kernel,
                         cudaFuncAttributeMaxDynamicSharedMemorySize, SMEM_BYTES);

    mask_kernel<<<dim3(Nb * T, 2), 128>>>(Q, K);
    proj_kernel<<<dim3(H / 64, (Nb * T) / 64, 3), 256>>>(Q, K, V,
                                                         Wq, Wk, Wv,
                                                         bq, bk, bv);
    attn_kernel<<<dim3(T / 128, NH, Nb), 256, SMEM_BYTES>>>();
    ln_kernel<<<Nb * T, 256>>>(gamma, beta, out, wout);
}

// round 8
// speedup vs baseline: 1.1942x; 1.1942x over previous
#include <cuda_runtime.h>
#include <cstdint>
#include <math.h>

#define Nb 2
#define T  2048
#define H  256
#define NH 8
#define D  32
#define SCALE 17.677669529663689f

typedef unsigned long long u64;
typedef uint32_t u32;

__device__ __forceinline__ void fma2(u64& d, u64 a, u64 b) {
    asm("fma.rn.f32x2 %0, %1, %2, %0;" : "+l"(d) : "l"(a), "l"(b));
}
__device__ __forceinline__ u64 pack2(float x, float y) {
    u64 r; asm("mov.b64 %0, {%1, %2};" : "=l"(r) : "f"(x), "f"(y)); return r;
}
__device__ __forceinline__ float2 unpack2(u64 v) {
    float2 f; asm("mov.b64 {%0, %1}, %2;" : "=f"(f.x), "=f"(f.y) : "l"(v)); return f;
}
__device__ __forceinline__ u32 tf32_hi(float x) {
    u32 h; asm("cvt.rna.tf32.f32 %0, %1;" : "=r"(h) : "f"(x)); return h;
}
__device__ __forceinline__ void tf32_split(float x, u32& hi, u32& lo) {
    hi = tf32_hi(x);
    lo = tf32_hi(x - __uint_as_float(hi));
}
#define MMA(c, a, b0, b1) \
    asm volatile("mma.sync.aligned.m16n8k8.row.col.f32.tf32.tf32.f32 " \
        "{%0,%1,%2,%3}, {%4,%5,%6,%7}, {%8,%9}, {%0,%1,%2,%3};" \
        : "+f"((c)[0]), "+f"((c)[1]), "+f"((c)[2]), "+f"((c)[3]) \
        : "r"((a)[0]), "r"((a)[1]), "r"((a)[2]), "r"((a)[3]), "r"(b0), "r"(b1))

__device__ __align__(16) float g_Qh[Nb*NH*T*D];
__device__ __align__(16) float g_Kh[Nb*NH*T*D];
__device__ __align__(16) float g_Vh[Nb*NH*T*D];
__device__ __align__(16) float g_ctx[Nb*T*H];
__device__ float g_kbias[Nb*T];   /* 0 or -1e35 */
__device__ float g_qmask[Nb*T];

/* ------------------------------------------------------------------ */
__global__ void mask_kernel(const float* __restrict__ Q,
                            const float* __restrict__ K) {
    int row = blockIdx.x;
    const float* src = blockIdx.y ? K : Q;
    int t = threadIdx.x;
    float s = fabsf(src[row*H + t]) + fabsf(src[row*H + t + 128]);
    __shared__ float red[4];
    #pragma unroll
    for (int o = 16; o; o >>= 1) s += __shfl_xor_sync(0xffffffffu, s, o);
    if ((t & 31) == 0) red[t >> 5] = s;
    __syncthreads();
    if (t == 0) {
        float tot = red[0] + red[1] + red[2] + red[3];
        if (blockIdx.y) g_kbias[row] = (tot != 0.0f) ? 0.0f : -1e35f;
        else            g_qmask[row] = (tot != 0.0f) ? 1.0f : 0.0f;
    }
}

/* ------------------------------------------------------------------ */
__global__ void __launch_bounds__(256) proj_kernel(
        const float* __restrict__ Q, const float* __restrict__ K,
        const float* __restrict__ V,
        const float* __restrict__ Wq, const float* __restrict__ Wk,
        const float* __restrict__ Wv,
        const float* __restrict__ bq, const float* __restrict__ bk,
        const float* __restrict__ bv) {
    int sel = blockIdx.z;
    const float* X = (sel == 0) ? Q  : (sel == 1) ? K  : V;
    const float* W = (sel == 0) ? Wq : (sel == 1) ? Wk : Wv;
    const float* b = (sel == 0) ? bq : (sel == 1) ? bk : bv;
    float* dst     = (sel == 0) ? g_Qh : (sel == 1) ? g_Kh : g_Vh;
    int m0 = blockIdx.y * 64, n0 = blockIdx.x * 64;
    __shared__ __align__(16) float Xst[32][68];
    __shared__ __align__(16) float Wsh[32][68];
    int tid = threadIdx.x, ty = tid >> 4, tx = tid & 15;
    u64 acc2[4][2] = {};
    for (int k0 = 0; k0 < H; k0 += 32) {
        __syncthreads();
        #pragma unroll
        for (int it = 0; it < 8; ++it) {
            int e = tid + it * 256;
            int r = e >> 5, c = e & 31;
            Xst[c][r] = X[(m0 + r) * H + k0 + c];
            int r2 = e >> 6, c2 = e & 63;
            Wsh[r2][c2] = W[(k0 + r2) * H + n0 + c2];
        }
        __syncthreads();
        #pragma unroll
        for (int kk = 0; kk < 32; ++kk) {
            float4 a = *(const float4*)&Xst[kk][4 * ty];
            ulonglong2 bb = *(const ulonglong2*)&Wsh[kk][4 * tx];
            u64 a0 = pack2(a.x, a.x), a1 = pack2(a.y, a.y);
            u64 a2 = pack2(a.z, a.z), a3 = pack2(a.w, a.w);
            fma2(acc2[0][0], a0, bb.x); fma2(acc2[0][1], a0, bb.y);
            fma2(acc2[1][0], a1, bb.x); fma2(acc2[1][1], a1, bb.y);
            fma2(acc2[2][0], a2, bb.x); fma2(acc2[2][1], a2, bb.y);
            fma2(acc2[3][0], a3, bb.x); fma2(acc2[3][1], a3, bb.y);
        }
    }
    int c0 = n0 + 4 * tx, hh = c0 >> 5, d0 = c0 & 31;
    float b0 = b[c0+0], b1 = b[c0+1], b2 = b[c0+2], b3 = b[c0+3];
    #pragma unroll
    for (int i = 0; i < 4; ++i) {
        int m = m0 + 4 * ty + i, nn = m >> 11, tt = m & 2047;
        float2 lo = unpack2(acc2[i][0]), hi = unpack2(acc2[i][1]);
        float4 o;
        o.x = fmaxf(lo.x + b0, 0.0f); o.y = fmaxf(lo.y + b1, 0.0f);
        o.z = fmaxf(hi.x + b2, 0.0f); o.w = fmaxf(hi.y + b3, 0.0f);
        *(float4*)&dst[(((nn * NH) + hh) * T + tt) * D + d0] = o;
    }
}

/* ------------------------------------------------------------------ */
/* 3xTF32 mma flash attention. Grid (16, NH, Nb), 128 thr (4 warps).  */
/* Warp owns 32 q-rows (2 m16 frags). PV = 2-term (P split, V hi).    */
#define KPITCH 68
#define VPITCH 36
#define PPITCH 36
#define SM_FLOATS (2*32*KPITCH + 64*VPITCH + 4*32*PPITCH + 64)
#define SMEM_BYTES (SM_FLOATS * 4)

__global__ void __launch_bounds__(128, 2) attn_kernel() {
    extern __shared__ __align__(16) float dsm[];
    float* Khi = dsm;                       /* [32][KPITCH] d-major   */
    float* Klo = Khi + 32 * KPITCH;
    float* Vhi = Klo + 32 * KPITCH;         /* [64][VPITCH] key-major */
    float* Ps  = Vhi + 64 * VPITCH;         /* [4][32][PPITCH]        */
    float* bias_s = Ps + 4 * 32 * PPITCH;

    int tid = threadIdx.x, w = tid >> 5, lane = tid & 31;
    int g = lane >> 2, tq = lane & 3;
    int q0 = blockIdx.x * 128, hh = blockIdx.y, nn = blockIdx.z;
    const float* Qg = g_Qh + (size_t)(nn * NH + hh) * T * D;
    const float* Kg = g_Kh + (size_t)(nn * NH + hh) * T * D;
    const float* Vg = g_Vh + (size_t)(nn * NH + hh) * T * D;
    float* Pw = Ps + w * 32 * PPITCH;

    /* Q fragments (loop-invariant): rows q0+32w+16m+g(+8), cols 8ks+tq(+4) */
    u32 qh[2][4][4], ql[2][4][4];
    #pragma unroll
    for (int m = 0; m < 2; ++m) {
        int r0 = (q0 + 32 * w + 16 * m + g) * D;
        int r1 = r0 + 8 * D;
        #pragma unroll
        for (int ks = 0; ks < 4; ++ks) {
            tf32_split(Qg[r0 + 8*ks + tq],     qh[m][ks][0], ql[m][ks][0]);
            tf32_split(Qg[r1 + 8*ks + tq],     qh[m][ks][1], ql[m][ks][1]);
            tf32_split(Qg[r0 + 8*ks + tq + 4], qh[m][ks][2], ql[m][ks][2]);
            tf32_split(Qg[r1 + 8*ks + tq + 4], qh[m][ks][3], ql[m][ks][3]);
        }
    }
    float O[2][4][4];
    #pragma unroll
    for (int m = 0; m < 2; ++m)
        #pragma unroll
        for (int nf = 0; nf < 4; ++nf)
            #pragma unroll
            for (int c = 0; c < 4; ++c) O[m][nf][c] = 0.0f;
    float mrun[2][2] = {{-1e30f,-1e30f},{-1e30f,-1e30f}};
    float lrun[2][2] = {{0.f,0.f},{0.f,0.f}};

    for (int kt = 0; kt < T / 64; ++kt) {
        int k0 = kt * 64;
        __syncthreads();
        #pragma unroll
        for (int i = 0; i < 16; ++i) {     /* K hi/lo + V hi -> smem */
            int idx = tid + 128 * i;
            int row = idx >> 5, c = idx & 31;
            u32 hb, lb;
            tf32_split(Kg[(k0 + row) * D + c], hb, lb);
            Khi[c * KPITCH + row] = __uint_as_float(hb);
            Klo[c * KPITCH + row] = __uint_as_float(lb);
            Vhi[row * VPITCH + c] =
                __uint_as_float(tf32_hi(Vg[(k0 + row) * D + c]));
        }
        if (tid < 64) bias_s[tid] = g_kbias[nn * T + k0 + tid];
        __syncthreads();

        #pragma unroll
        for (int h = 0; h < 2; ++h) {
            /* ---- S = Q K^T (3xTF32) ---- */
            float s[2][4][4];
            #pragma unroll
            for (int m = 0; m < 2; ++m)
                #pragma unroll
                for (int j = 0; j < 4; ++j)
                    #pragma unroll
                    for (int c = 0; c < 4; ++c) s[m][j][c] = 0.0f;
            #pragma unroll
            for (int ks = 0; ks < 4; ++ks) {
                u32 bh[4][2], bl[4][2];
                #pragma unroll
                for (int j = 0; j < 4; ++j) {
                    int col = 32 * h + 8 * j + g;
                    bh[j][0] = __float_as_uint(Khi[(8*ks + tq)     * KPITCH + col]);
                    bh[j][1] = __float_as_uint(Khi[(8*ks + tq + 4) * KPITCH + col]);
                    bl[j][0] = __float_as_uint(Klo[(8*ks + tq)     * KPITCH + col]);
                    bl[j][1] = __float_as_uint(Klo[(8*ks + tq + 4) * KPITCH + col]);
                }
                #pragma unroll
                for (int m = 0; m < 2; ++m)
                    #pragma unroll
                    for (int j = 0; j < 4; ++j) {
                        MMA(s[m][j], qh[m][ks], bh[j][0], bh[j][1]);
                        MMA(s[m][j], ql[m][ks], bh[j][0], bh[j][1]);
                        MMA(s[m][j], qh[m][ks], bl[j][0], bl[j][1]);
                    }
            }

            /* ---- softmax (fragment-resident) ---- */
            float2 bb[4];
            #pragma unroll
            for (int j = 0; j < 4; ++j)
                bb[j] = *(float2*)&bias_s[32 * h + 8 * j + 2 * tq];
            #pragma unroll
            for (int m = 0; m < 2; ++m)
                #pragma unroll
                for (int rg = 0; rg < 2; ++rg) {
                    float zv[8];
                    #pragma unroll
                    for (int j = 0; j < 4; ++j) {
                        zv[2*j]   = fmaf(s[m][j][2*rg],   SCALE, bb[j].x);
                        zv[2*j+1] = fmaf(s[m][j][2*rg+1], SCALE, bb[j].y);
                    }
                    float mx = zv[0];
                    #pragma unroll
                    for (int e = 1; e < 8; ++e) mx = fmaxf(mx, zv[e]);
                    mx = fmaxf(mx, __shfl_xor_sync(0xffffffffu, mx, 1));
                    mx = fmaxf(mx, __shfl_xor_sync(0xffffffffu, mx, 2));
                    float mn = fmaxf(mrun[m][rg], mx);
                    float fr = __expf(mrun[m][rg] - mn);
                    mrun[m][rg] = mn;
                    float sum = 0.0f;
                    #pragma unroll
                    for (int j = 0; j < 4; ++j) {
                        float p0 = __expf(zv[2*j]   - mn);
                        float p1 = __expf(zv[2*j+1] - mn);
                        sum += p0 + p1;
                        s[m][j][2*rg] = p0; s[m][j][2*rg+1] = p1;
                    }
                    sum += __shfl_xor_sync(0xffffffffu, sum, 1);
                    sum += __shfl_xor_sync(0xffffffffu, sum, 2);
                    lrun[m][rg] = lrun[m][rg] * fr + sum;
                    #pragma unroll
                    for (int nf = 0; nf < 4; ++nf) {
                        O[m][nf][2*rg]   *= fr;
                        O[m][nf][2*rg+1] *= fr;
                    }
                }

            /* ---- P -> per-warp smem (zero last key in ctx) ---- */
            __syncwarp();
            int kb = k0 + 32 * h + 2 * tq;
            #pragma unroll
            for (int m = 0; m < 2; ++m)
                #pragma unroll
                for (int j = 0; j < 4; ++j) {
                    float p1 = s[m][j][1], p3 = s[m][j][3];
                    if (kb + 8*j + 1 == T - 1) { p1 = 0.0f; p3 = 0.0f; }
                    *(float2*)&Pw[(16*m + g)     * PPITCH + 8*j + 2*tq] =
                        make_float2(s[m][j][0], p1);
                    *(float2*)&Pw[(16*m + 8 + g) * PPITCH + 8*j + 2*tq] =
                        make_float2(s[m][j][2], p3);
                }
            __syncwarp();

            /* ---- O += P V (2-term: (Phi+Plo) x Vhi) ---- */
            #pragma unroll
            for (int ks = 0; ks < 4; ++ks) {
                u32 ph[2][4], pl[2][4];
                #pragma unroll
                for (int m = 0; m < 2; ++m) {
                    tf32_split(Pw[(16*m + g)   * PPITCH + 8*ks + tq],     ph[m][0], pl[m][0]);
                    tf32_split(Pw[(16*m + 8+g) * PPITCH + 8*ks + tq],     ph[m][1], pl[m][1]);
                    tf32_split(Pw[(16*m + g)   * PPITCH + 8*ks + tq + 4], ph[m][2], pl[m][2]);
                    tf32_split(Pw[(16*m + 8+g) * PPITCH + 8*ks + tq + 4], ph[m][3], pl[m][3]);
                }
                int krow0 = (32*h + 8*ks + tq) * VPITCH;
                int krow1 = (32*h + 8*ks + tq + 4) * VPITCH;
                #pragma unroll
                for (int nf = 0; nf < 4; ++nf) {
                    u32 vh0 = __float_as_uint(Vhi[krow0 + 8*nf + g]);
                    u32 vh1 = __float_as_uint(Vhi[krow1 + 8*nf + g]);
                    #pragma unroll
                    for (int m = 0; m < 2; ++m) {
                        MMA(O[m][nf], ph[m], vh0, vh1);
                        MMA(O[m][nf], pl[m], vh0, vh1);
                    }
                }
            }
        }
    }

    /* ---- epilogue ---- */
    #pragma unroll
    for (int m = 0; m < 2; ++m)
        #pragma unroll
        for (int rg = 0; rg < 2; ++rg) {
            int row = q0 + 32 * w + 16 * m + 8 * rg + g;
            float inv = g_qmask[nn * T + row] / lrun[m][rg];
            float* dst = &g_ctx[(size_t)(nn * T + row) * H + hh * D];
            #pragma unroll
            for (int nf = 0; nf < 4; ++nf)
                *(float2*)&dst[8*nf + 2*tq] =
                    make_float2(O[m][nf][2*rg] * inv, O[m][nf][2*rg+1] * inv);
        }
}

/* ------------------------------------------------------------------ */
__global__ void __launch_bounds__(256) ln_kernel(
        const float* __restrict__ gamma, const float* __restrict__ beta,
        float* __restrict__ out, float* __restrict__ wout) {
    int row = blockIdx.x, t = threadIdx.x;
    float x = g_ctx[(size_t)row * H + t];
    __shared__ float rs[8], rq[8];
    float s = x, q = x * x;
    #pragma unroll
    for (int o = 16; o; o >>= 1) {
        s += __shfl_xor_sync(0xffffffffu, s, o);
        q += __shfl_xor_sync(0xffffffffu, q, o);
    }
    if ((t & 31) == 0) { rs[t >> 5] = s; rq[t >> 5] = q; }
    __syncthreads();
    float ts = 0.0f, tq = 0.0f;
    #pragma unroll
    for (int i = 0; i < 8; ++i) { ts += rs[i]; tq += rq[i]; }
    float mu = ts * (1.0f / H);
    float var = tq * (1.0f / H) - mu * mu;
    float inv = rsqrtf(var + 1e-5f);
    out[(size_t)row * H + t] = (x - mu) * inv * gamma[t] + beta[t];
    if (t == 0) wout[row] = g_qmask[row] * (1.0f / (float)T);
}

/* ------------------------------------------------------------------ */
extern "C" void kernel_launch(void* const* d_in, const int* in_sizes, int n_in,
                              void* d_out, int out_size) {
    const float* Q  = (const float*)d_in[0];
    const float* K  = (const float*)d_in[1];
    const float* V  = (const float*)d_in[2];
    const float* Wq = (const float*)d_in[3];
    const float* bq = (const float*)d_in[4];
    const float* Wk = (const float*)d_in[5];
    const float* bk = (const float*)d_in[6];
    const float* Wv = (const float*)d_in[7];
    const float* bv = (const float*)d_in[8];
    const float* gamma = (const float*)d_in[9];
    const float* beta  = (const float*)d_in[10];

    float* out  = (float*)d_out;
    float* wout = out + (out_size - Nb * T);

    cudaFuncSetAttribute(attn_kernel,
                         cudaFuncAttributeMaxDynamicSharedMemorySize, SMEM_BYTES);

    mask_kernel<<<dim3(Nb * T, 2), 128>>>(Q, K);
    proj_kernel<<<dim3(H / 64, (Nb * T) / 64, 3), 256>>>(Q, K, V,
                                                         Wq, Wk, Wv,
                                                         bq, bk, bv);
    attn_kernel<<<dim3(T / 128, NH, Nb), 128, SMEM_BYTES>>>();
    ln_kernel<<<Nb * T, 256>>>(gamma, beta, out, wout);
}

// round 9
// speedup vs baseline: 1.2822x; 1.0737x over previous
#include <cuda_runtime.h>
#include <cstdint>
#include <math.h>

#define Nb 2
#define T  2048
#define H  256
#define NH 8
#define D  32
#define SCALE 17.677669529663689f

typedef unsigned long long u64;
typedef uint32_t u32;

__device__ __forceinline__ void fma2(u64& d, u64 a, u64 b) {
    asm("fma.rn.f32x2 %0, %1, %2, %0;" : "+l"(d) : "l"(a), "l"(b));
}
__device__ __forceinline__ u64 pack2(float x, float y) {
    u64 r; asm("mov.b64 %0, {%1, %2};" : "=l"(r) : "f"(x), "f"(y)); return r;
}
__device__ __forceinline__ float2 unpack2(u64 v) {
    float2 f; asm("mov.b64 {%0, %1}, %2;" : "=f"(f.x), "=f"(f.y) : "l"(v)); return f;
}
__device__ __forceinline__ u32 tf32_hi(float x) {
    u32 h; asm("cvt.rna.tf32.f32 %0, %1;" : "=r"(h) : "f"(x)); return h;
}
__device__ __forceinline__ void tf32_split(float x, u32& hi, u32& lo) {
    hi = tf32_hi(x);
    lo = tf32_hi(x - __uint_as_float(hi));
}
#define MMA(c, a, b0, b1) \
    asm volatile("mma.sync.aligned.m16n8k8.row.col.f32.tf32.tf32.f32 " \
        "{%0,%1,%2,%3}, {%4,%5,%6,%7}, {%8,%9}, {%0,%1,%2,%3};" \
        : "+f"((c)[0]), "+f"((c)[1]), "+f"((c)[2]), "+f"((c)[3]) \
        : "r"((a)[0]), "r"((a)[1]), "r"((a)[2]), "r"((a)[3]), "r"(b0), "r"(b1))

__device__ __align__(16) float g_Qh[Nb*NH*T*D];
__device__ __align__(16) float g_Kh[Nb*NH*T*D];
__device__ __align__(16) float g_Vh[Nb*NH*T*D];
__device__ __align__(16) float g_ctx[Nb*T*H];
__device__ float g_kbias[Nb*T];   /* 0 or -1e35 */
__device__ float g_qmask[Nb*T];

/* ------------------------------------------------------------------ */
__global__ void mask_kernel(const float* __restrict__ Q,
                            const float* __restrict__ K) {
    int row = blockIdx.x;
    const float* src = blockIdx.y ? K : Q;
    int t = threadIdx.x;
    float s = fabsf(src[row*H + t]) + fabsf(src[row*H + t + 128]);
    __shared__ float red[4];
    #pragma unroll
    for (int o = 16; o; o >>= 1) s += __shfl_xor_sync(0xffffffffu, s, o);
    if ((t & 31) == 0) red[t >> 5] = s;
    __syncthreads();
    if (t == 0) {
        float tot = red[0] + red[1] + red[2] + red[3];
        if (blockIdx.y) g_kbias[row] = (tot != 0.0f) ? 0.0f : -1e35f;
        else            g_qmask[row] = (tot != 0.0f) ? 1.0f : 0.0f;
    }
}

/* ------------------------------------------------------------------ */
__global__ void __launch_bounds__(256) proj_kernel(
        const float* __restrict__ Q, const float* __restrict__ K,
        const float* __restrict__ V,
        const float* __restrict__ Wq, const float* __restrict__ Wk,
        const float* __restrict__ Wv,
        const float* __restrict__ bq, const float* __restrict__ bk,
        const float* __restrict__ bv) {
    int sel = blockIdx.z;
    const float* X = (sel == 0) ? Q  : (sel == 1) ? K  : V;
    const float* W = (sel == 0) ? Wq : (sel == 1) ? Wk : Wv;
    const float* b = (sel == 0) ? bq : (sel == 1) ? bk : bv;
    float* dst     = (sel == 0) ? g_Qh : (sel == 1) ? g_Kh : g_Vh;
    int m0 = blockIdx.y * 64, n0 = blockIdx.x * 64;
    __shared__ __align__(16) float Xst[32][68];
    __shared__ __align__(16) float Wsh[32][68];
    int tid = threadIdx.x, ty = tid >> 4, tx = tid & 15;
    u64 acc2[4][2] = {};
    for (int k0 = 0; k0 < H; k0 += 32) {
        __syncthreads();
        #pragma unroll
        for (int it = 0; it < 8; ++it) {
            int e = tid + it * 256;
            int r = e >> 5, c = e & 31;
            Xst[c][r] = X[(m0 + r) * H + k0 + c];
            int r2 = e >> 6, c2 = e & 63;
            Wsh[r2][c2] = W[(k0 + r2) * H + n0 + c2];
        }
        __syncthreads();
        #pragma unroll
        for (int kk = 0; kk < 32; ++kk) {
            float4 a = *(const float4*)&Xst[kk][4 * ty];
            ulonglong2 bb = *(const ulonglong2*)&Wsh[kk][4 * tx];
            u64 a0 = pack2(a.x, a.x), a1 = pack2(a.y, a.y);
            u64 a2 = pack2(a.z, a.z), a3 = pack2(a.w, a.w);
            fma2(acc2[0][0], a0, bb.x); fma2(acc2[0][1], a0, bb.y);
            fma2(acc2[1][0], a1, bb.x); fma2(acc2[1][1], a1, bb.y);
            fma2(acc2[2][0], a2, bb.x); fma2(acc2[2][1], a2, bb.y);
            fma2(acc2[3][0], a3, bb.x); fma2(acc2[3][1], a3, bb.y);
        }
    }
    int c0 = n0 + 4 * tx, hh = c0 >> 5, d0 = c0 & 31;
    float b0 = b[c0+0], b1 = b[c0+1], b2 = b[c0+2], b3 = b[c0+3];
    #pragma unroll
    for (int i = 0; i < 4; ++i) {
        int m = m0 + 4 * ty + i, nn = m >> 11, tt = m & 2047;
        float2 lo = unpack2(acc2[i][0]), hi = unpack2(acc2[i][1]);
        float4 o;
        o.x = fmaxf(lo.x + b0, 0.0f); o.y = fmaxf(lo.y + b1, 0.0f);
        o.z = fmaxf(hi.x + b2, 0.0f); o.w = fmaxf(hi.y + b3, 0.0f);
        *(float4*)&dst[(((nn * NH) + hh) * T + tt) * D + d0] = o;
    }
}

/* ------------------------------------------------------------------ */
/* 3xTF32 mma flash attention, paired smem layouts.                   */
/* Grid (16, NH, Nb), 128 thr (4 warps), warp = 32 q-rows.            */
#define KP4PITCH 66   /* float4 units */
#define VP2PITCH 36   /* float2 units */
#define PP2PITCH 36   /* float2 units */
#define SM_FLOATS (16*KP4PITCH*4 + 32*VP2PITCH*2 + 4*16*PP2PITCH*2 + 64)
#define SMEM_BYTES (SM_FLOATS * 4)

__global__ void __launch_bounds__(128, 2) attn_kernel() {
    extern __shared__ __align__(16) float dsm[];
    float4* KP4 = (float4*)dsm;                       /* [16][66] */
    float2* VP2 = (float2*)(dsm + 16 * KP4PITCH * 4); /* [32][36] */
    float2* PP2 = VP2 + 32 * VP2PITCH;                /* [4][16][36] */
    float*  bias_s = (float*)(PP2 + 4 * 16 * PP2PITCH);

    int tid = threadIdx.x, w = tid >> 5, lane = tid & 31;
    int g = lane >> 2, tq = lane & 3;
    int q0 = blockIdx.x * 128, hh = blockIdx.y, nn = blockIdx.z;
    const float* Qg = g_Qh + (size_t)(nn * NH + hh) * T * D;
    const float* Kg = g_Kh + (size_t)(nn * NH + hh) * T * D;
    const float* Vg = g_Vh + (size_t)(nn * NH + hh) * T * D;
    float2* Pw2 = PP2 + w * 16 * PP2PITCH;

    /* Q fragments (loop-invariant) */
    u32 qh[2][4][4], ql[2][4][4];
    #pragma unroll
    for (int m = 0; m < 2; ++m) {
        int r0 = (q0 + 32 * w + 16 * m + g) * D;
        int r1 = r0 + 8 * D;
        #pragma unroll
        for (int ks = 0; ks < 4; ++ks) {
            tf32_split(Qg[r0 + 8*ks + tq],     qh[m][ks][0], ql[m][ks][0]);
            tf32_split(Qg[r1 + 8*ks + tq],     qh[m][ks][1], ql[m][ks][1]);
            tf32_split(Qg[r0 + 8*ks + tq + 4], qh[m][ks][2], ql[m][ks][2]);
            tf32_split(Qg[r1 + 8*ks + tq + 4], qh[m][ks][3], ql[m][ks][3]);
        }
    }
    float O[2][4][4];
    #pragma unroll
    for (int m = 0; m < 2; ++m)
        #pragma unroll
        for (int nf = 0; nf < 4; ++nf)
            #pragma unroll
            for (int c = 0; c < 4; ++c) O[m][nf][c] = 0.0f;
    float mrun[2][2] = {{-1e30f,-1e30f},{-1e30f,-1e30f}};
    float lrun[2][2] = {{0.f,0.f},{0.f,0.f}};

    for (int kt = 0; kt < T / 64; ++kt) {
        int k0 = kt * 64;
        __syncthreads();
        /* ---- fill: K pairs (d,d+4) hi/lo as float4; V pairs (r,r+4) ---- */
        #pragma unroll
        for (int i = 0; i < 8; ++i) {
            int idx = tid + 128 * i;
            /* K: dgrp fast (coalesced: 16 lanes cover half a key-row) */
            int dgrp = idx & 15, key = idx >> 4;
            int dlo = 8 * (dgrp >> 2) + (dgrp & 3);
            u32 h0, l0, h1, l1;
            tf32_split(Kg[(k0 + key) * D + dlo],     h0, l0);
            tf32_split(Kg[(k0 + key) * D + dlo + 4], h1, l1);
            float4 kf;
            kf.x = __uint_as_float(h0); kf.y = __uint_as_float(h1);
            kf.z = __uint_as_float(l0); kf.w = __uint_as_float(l1);
            KP4[dgrp * KP4PITCH + key] = kf;
            /* V: d fast (fully coalesced rows) */
            int d = idx & 31, kgrp = idx >> 5;
            int rlo = 8 * (kgrp >> 2) + (kgrp & 3);
            float2 vf;
            vf.x = __uint_as_float(tf32_hi(Vg[(k0 + rlo) * D + d]));
            vf.y = __uint_as_float(tf32_hi(Vg[(k0 + rlo + 4) * D + d]));
            VP2[kgrp * VP2PITCH + d] = vf;
        }
        if (tid < 64) bias_s[tid] = g_kbias[nn * T + k0 + tid];
        __syncthreads();

        #pragma unroll
        for (int h = 0; h < 2; ++h) {
            /* ---- S = Q K^T (3xTF32), one LDS.128 per B-frag ---- */
            float s[2][4][4];
            #pragma unroll
            for (int m = 0; m < 2; ++m)
                #pragma unroll
                for (int j = 0; j < 4; ++j)
                    #pragma unroll
                    for (int c = 0; c < 4; ++c) s[m][j][c] = 0.0f;
            #pragma unroll
            for (int ks = 0; ks < 4; ++ks) {
                float4 kf[4];
                #pragma unroll
                for (int j = 0; j < 4; ++j)
                    kf[j] = KP4[(4*ks + tq) * KP4PITCH + 32*h + 8*j + g];
                #pragma unroll
                for (int m = 0; m < 2; ++m)
                    #pragma unroll
                    for (int j = 0; j < 4; ++j) {
                        u32 bh0 = __float_as_uint(kf[j].x);
                        u32 bh1 = __float_as_uint(kf[j].y);
                        u32 bl0 = __float_as_uint(kf[j].z);
                        u32 bl1 = __float_as_uint(kf[j].w);
                        MMA(s[m][j], qh[m][ks], bh0, bh1);
                        MMA(s[m][j], ql[m][ks], bh0, bh1);
                        MMA(s[m][j], qh[m][ks], bl0, bl1);
                    }
            }

            /* ---- softmax (fragment-resident) ---- */
            float2 bb[4];
            #pragma unroll
            for (int j = 0; j < 4; ++j)
                bb[j] = *(float2*)&bias_s[32 * h + 8 * j + 2 * tq];
            #pragma unroll
            for (int m = 0; m < 2; ++m)
                #pragma unroll
                for (int rg = 0; rg < 2; ++rg) {
                    float zv[8];
                    #pragma unroll
                    for (int j = 0; j < 4; ++j) {
                        zv[2*j]   = fmaf(s[m][j][2*rg],   SCALE, bb[j].x);
                        zv[2*j+1] = fmaf(s[m][j][2*rg+1], SCALE, bb[j].y);
                    }
                    float mx = zv[0];
                    #pragma unroll
                    for (int e = 1; e < 8; ++e) mx = fmaxf(mx, zv[e]);
                    mx = fmaxf(mx, __shfl_xor_sync(0xffffffffu, mx, 1));
                    mx = fmaxf(mx, __shfl_xor_sync(0xffffffffu, mx, 2));
                    float mn = fmaxf(mrun[m][rg], mx);
                    float fr = __expf(mrun[m][rg] - mn);
                    mrun[m][rg] = mn;
                    float sum = 0.0f;
                    #pragma unroll
                    for (int j = 0; j < 4; ++j) {
                        float p0 = __expf(zv[2*j]   - mn);
                        float p1 = __expf(zv[2*j+1] - mn);
                        sum += p0 + p1;
                        s[m][j][2*rg] = p0; s[m][j][2*rg+1] = p1;
                    }
                    sum += __shfl_xor_sync(0xffffffffu, sum, 1);
                    sum += __shfl_xor_sync(0xffffffffu, sum, 2);
                    lrun[m][rg] = lrun[m][rg] * fr + sum;
                    #pragma unroll
                    for (int nf = 0; nf < 4; ++nf) {
                        O[m][nf][2*rg]   *= fr;
                        O[m][nf][2*rg+1] *= fr;
                    }
                }

            /* ---- P -> paired smem {row g, row g+8}, one STS.128 ---- */
            __syncwarp();
            int kb = k0 + 32 * h + 2 * tq;
            #pragma unroll
            for (int m = 0; m < 2; ++m)
                #pragma unroll
                for (int j = 0; j < 4; ++j) {
                    float p1 = s[m][j][1], p3 = s[m][j][3];
                    if (kb + 8*j + 1 == T - 1) { p1 = 0.0f; p3 = 0.0f; }
                    float4 pv;
                    pv.x = s[m][j][0]; pv.y = s[m][j][2];  /* col 2tq   */
                    pv.z = p1;         pv.w = p3;          /* col 2tq+1 */
                    *(float4*)&Pw2[(8*m + g) * PP2PITCH + 8*j + 2*tq] = pv;
                }
            __syncwarp();

            /* ---- O += P V (2-term), LDS.64 pairs ---- */
            #pragma unroll
            for (int ks = 0; ks < 4; ++ks) {
                u32 ph[2][4], pl[2][4];
                #pragma unroll
                for (int m = 0; m < 2; ++m) {
                    float2 pa = Pw2[(8*m + g) * PP2PITCH + 8*ks + tq];
                    float2 pb = Pw2[(8*m + g) * PP2PITCH + 8*ks + tq + 4];
                    tf32_split(pa.x, ph[m][0], pl[m][0]);
                    tf32_split(pa.y, ph[m][1], pl[m][1]);
                    tf32_split(pb.x, ph[m][2], pl[m][2]);
                    tf32_split(pb.y, ph[m][3], pl[m][3]);
                }
                #pragma unroll
                for (int nf = 0; nf < 4; ++nf) {
                    float2 vv = VP2[(16*h + 4*ks + tq) * VP2PITCH + 8*nf + g];
                    u32 vh0 = __float_as_uint(vv.x);
                    u32 vh1 = __float_as_uint(vv.y);
                    #pragma unroll
                    for (int m = 0; m < 2; ++m) {
                        MMA(O[m][nf], ph[m], vh0, vh1);
                        MMA(O[m][nf], pl[m], vh0, vh1);
                    }
                }
            }
        }
    }

    /* ---- epilogue ---- */
    #pragma unroll
    for (int m = 0; m < 2; ++m)
        #pragma unroll
        for (int rg = 0; rg < 2; ++rg) {
            int row = q0 + 32 * w + 16 * m + 8 * rg + g;
            float inv = g_qmask[nn * T + row] / lrun[m][rg];
            float* dst = &g_ctx[(size_t)(nn * T + row) * H + hh * D];
            #pragma unroll
            for (int nf = 0; nf < 4; ++nf)
                *(float2*)&dst[8*nf + 2*tq] =
                    make_float2(O[m][nf][2*rg] * inv, O[m][nf][2*rg+1] * inv);
        }
}

/* ------------------------------------------------------------------ */
__global__ void __launch_bounds__(256) ln_kernel(
        const float* __restrict__ gamma, const float* __restrict__ beta,
        float* __restrict__ out, float* __restrict__ wout) {
    int row = blockIdx.x, t = threadIdx.x;
    float x = g_ctx[(size_t)row * H + t];
    __shared__ float rs[8], rq[8];
    float s = x, q = x * x;
    #pragma unroll
    for (int o = 16; o; o >>= 1) {
        s += __shfl_xor_sync(0xffffffffu, s, o);
        q += __shfl_xor_sync(0xffffffffu, q, o);
    }
    if ((t & 31) == 0) { rs[t >> 5] = s; rq[t >> 5] = q; }
    __syncthreads();
    float ts = 0.0f, tq = 0.0f;
    #pragma unroll
    for (int i = 0; i < 8; ++i) { ts += rs[i]; tq += rq[i]; }
    float mu = ts * (1.0f / H);
    float var = tq * (1.0f / H) - mu * mu;
    float inv = rsqrtf(var + 1e-5f);
    out[(size_t)row * H + t] = (x - mu) * inv * gamma[t] + beta[t];
    if (t == 0) wout[row] = g_qmask[row] * (1.0f / (float)T);
}

/* ------------------------------------------------------------------ */
extern "C" void kernel_launch(void* const* d_in, const int* in_sizes, int n_in,
                              void* d_out, int out_size) {
    const float* Q  = (const float*)d_in[0];
    const float* K  = (const float*)d_in[1];
    const float* V  = (const float*)d_in[2];
    const float* Wq = (const float*)d_in[3];
    const float* bq = (const float*)d_in[4];
    const float* Wk = (const float*)d_in[5];
    const float* bk = (const float*)d_in[6];
    const float* Wv = (const float*)d_in[7];
    const float* bv = (const float*)d_in[8];
    const float* gamma = (const float*)d_in[9];
    const float* beta  = (const float*)d_in[10];

    float* out  = (float*)d_out;
    float* wout = out + (out_size - Nb * T);

    cudaFuncSetAttribute(attn_kernel,
                         cudaFuncAttributeMaxDynamicSharedMemorySize, SMEM_BYTES);

    mask_kernel<<<dim3(Nb * T, 2), 128>>>(Q, K);
    proj_kernel<<<dim3(H / 64, (Nb * T) / 64, 3), 256>>>(Q, K, V,
                                                         Wq, Wk, Wv,
                                                         bq, bk, bv);
    attn_kernel<<<dim3(T / 128, NH, Nb), 128, SMEM_BYTES>>>();
    ln_kernel<<<Nb * T, 256>>>(gamma, beta, out, wout);
}

// round 10
// speedup vs baseline: 1.3428x; 1.0472x over previous
#include <cuda_runtime.h>
#include <cstdint>
#include <math.h>

#define Nb 2
#define T  2048
#define H  256
#define NH 8
#define D  32
#define SCALE 17.677669529663689f

typedef unsigned long long u64;
typedef uint32_t u32;

__device__ __forceinline__ void fma2(u64& d, u64 a, u64 b) {
    asm("fma.rn.f32x2 %0, %1, %2, %0;" : "+l"(d) : "l"(a), "l"(b));
}
__device__ __forceinline__ u64 pack2(float x, float y) {
    u64 r; asm("mov.b64 %0, {%1, %2};" : "=l"(r) : "f"(x), "f"(y)); return r;
}
__device__ __forceinline__ float2 unpack2(u64 v) {
    float2 f; asm("mov.b64 {%0, %1}, %2;" : "=f"(f.x), "=f"(f.y) : "l"(v)); return f;
}
__device__ __forceinline__ u32 tf32_hi(float x) {
    u32 h; asm("cvt.rna.tf32.f32 %0, %1;" : "=r"(h) : "f"(x)); return h;
}
__device__ __forceinline__ void tf32_split(float x, u32& hi, u32& lo) {
    hi = tf32_hi(x);
    lo = tf32_hi(x - __uint_as_float(hi));
}
__device__ __forceinline__ u32 smem_u32(const void* p) {
    u32 a;
    asm("{ .reg .u64 t; cvta.to.shared.u64 t, %1; cvt.u32.u64 %0, t; }" : "=r"(a) : "l"(p));
    return a;
}
__device__ __forceinline__ void cpa16(u32 saddr, const void* g) {
    asm volatile("cp.async.cg.shared.global [%0], [%1], 16;" :: "r"(saddr), "l"(g));
}
#define CPA_COMMIT() asm volatile("cp.async.commit_group;" ::: "memory")
#define CPA_WAIT1()  asm volatile("cp.async.wait_group 1;"  ::: "memory")
#define CPA_WAIT0()  asm volatile("cp.async.wait_group 0;"  ::: "memory")
#define MMA(c, a, b0, b1) \
    asm volatile("mma.sync.aligned.m16n8k8.row.col.f32.tf32.tf32.f32 " \
        "{%0,%1,%2,%3}, {%4,%5,%6,%7}, {%8,%9}, {%0,%1,%2,%3};" \
        : "+f"((c)[0]), "+f"((c)[1]), "+f"((c)[2]), "+f"((c)[3]) \
        : "r"((a)[0]), "r"((a)[1]), "r"((a)[2]), "r"((a)[3]), "r"(b0), "r"(b1))

__device__ __align__(16) float g_Qh[Nb*NH*T*D];        /* [n][h][t][d] fp32 */
__device__ __align__(16) float4 g_Kp[Nb*NH*32*1024];   /* packed K tiles    */
__device__ __align__(16) float2 g_Vp[Nb*NH*32*1024];   /* packed V tiles    */
__device__ __align__(16) float g_ctx[Nb*T*H];
__device__ float g_kbias[Nb*T];   /* 0 or -1e35 */
__device__ float g_qmask[Nb*T];

/* ------------------------------------------------------------------ */
__global__ void mask_kernel(const float* __restrict__ Q,
                            const float* __restrict__ K) {
    int row = blockIdx.x;
    const float* src = blockIdx.y ? K : Q;
    int t = threadIdx.x;
    float s = fabsf(src[row*H + t]) + fabsf(src[row*H + t + 128]);
    __shared__ float red[4];
    #pragma unroll
    for (int o = 16; o; o >>= 1) s += __shfl_xor_sync(0xffffffffu, s, o);
    if ((t & 31) == 0) red[t >> 5] = s;
    __syncthreads();
    if (t == 0) {
        float tot = red[0] + red[1] + red[2] + red[3];
        if (blockIdx.y) g_kbias[row] = (tot != 0.0f) ? 0.0f : -1e35f;
        else            g_qmask[row] = (tot != 0.0f) ? 1.0f : 0.0f;
    }
}

/* ------------------------------------------------------------------ */
/* Projection. sel 0: Q -> g_Qh fp32. sel 1: K -> packed hi/lo tiles. */
/* sel 2: V -> packed hi tiles.                                       */
__global__ void __launch_bounds__(256) proj_kernel(
        const float* __restrict__ Q, const float* __restrict__ K,
        const float* __restrict__ V,
        const float* __restrict__ Wq, const float* __restrict__ Wk,
        const float* __restrict__ Wv,
        const float* __restrict__ bq, const float* __restrict__ bk,
        const float* __restrict__ bv) {
    int sel = blockIdx.z;
    const float* X = (sel == 0) ? Q  : (sel == 1) ? K  : V;
    const float* W = (sel == 0) ? Wq : (sel == 1) ? Wk : Wv;
    const float* b = (sel == 0) ? bq : (sel == 1) ? bk : bv;
    int m0 = blockIdx.y * 64, n0 = blockIdx.x * 64;
    __shared__ __align__(16) float Xst[32][68];
    __shared__ __align__(16) float Wsh[32][68];
    int tid = threadIdx.x, ty = tid >> 4, tx = tid & 15;
    u64 acc2[4][2] = {};
    for (int k0 = 0; k0 < H; k0 += 32) {
        __syncthreads();
        #pragma unroll
        for (int it = 0; it < 8; ++it) {
            int e = tid + it * 256;
            int r = e >> 5, c = e & 31;
            Xst[c][r] = X[(m0 + r) * H + k0 + c];
            int r2 = e >> 6, c2 = e & 63;
            Wsh[r2][c2] = W[(k0 + r2) * H + n0 + c2];
        }
        __syncthreads();
        #pragma unroll
        for (int kk = 0; kk < 32; ++kk) {
            float4 a = *(const float4*)&Xst[kk][4 * ty];
            ulonglong2 bb = *(const ulonglong2*)&Wsh[kk][4 * tx];
            u64 a0 = pack2(a.x, a.x), a1 = pack2(a.y, a.y);
            u64 a2 = pack2(a.z, a.z), a3 = pack2(a.w, a.w);
            fma2(acc2[0][0], a0, bb.x); fma2(acc2[0][1], a0, bb.y);
            fma2(acc2[1][0], a1, bb.x); fma2(acc2[1][1], a1, bb.y);
            fma2(acc2[2][0], a2, bb.x); fma2(acc2[2][1], a2, bb.y);
            fma2(acc2[3][0], a3, bb.x); fma2(acc2[3][1], a3, bb.y);
        }
    }
    int c0 = n0 + 4 * tx, hh = c0 >> 5, d0 = c0 & 31;
    float b0 = b[c0+0], b1 = b[c0+1], b2 = b[c0+2], b3 = b[c0+3];
    #pragma unroll
    for (int i = 0; i < 4; ++i) {
        int m = m0 + 4 * ty + i, nn = m >> 11, tt = m & 2047;
        float2 lo = unpack2(acc2[i][0]), hi = unpack2(acc2[i][1]);
        float v0 = fmaxf(lo.x + b0, 0.0f), v1 = fmaxf(lo.y + b1, 0.0f);
        float v2 = fmaxf(hi.x + b2, 0.0f), v3 = fmaxf(hi.y + b3, 0.0f);
        int tile = tt >> 6;
        size_t tbase = ((size_t)(nn * NH + hh) * 32 + tile) * 1024;
        if (sel == 0) {
            *(float4*)&g_Qh[(((size_t)(nn * NH) + hh) * T + tt) * D + d0] =
                make_float4(v0, v1, v2, v3);
        } else if (sel == 1) {
            int key = tt & 63;
            int q = d0 >> 3, sl = (d0 & 4) ? 1 : 0;
            u32 hb[4], lb[4];
            tf32_split(v0, hb[0], lb[0]); tf32_split(v1, hb[1], lb[1]);
            tf32_split(v2, hb[2], lb[2]); tf32_split(v3, hb[3], lb[3]);
            float* base = (float*)g_Kp + (tbase + key) * 4;
            #pragma unroll
            for (int j = 0; j < 4; ++j) {
                base[((4*q + j) * 64) * 4 + sl]     = __uint_as_float(hb[j]);
                base[((4*q + j) * 64) * 4 + sl + 2] = __uint_as_float(lb[j]);
            }
        } else {
            int rr = tt & 63;
            int q = rr >> 3, rm = rr & 7, kgrp = 4*q + (rm & 3), sl = rm >> 2;
            float* base = (float*)g_Vp + (tbase + kgrp * 32) * 2 + sl;
            base[(d0+0)*2] = __uint_as_float(tf32_hi(v0));
            base[(d0+1)*2] = __uint_as_float(tf32_hi(v1));
            base[(d0+2)*2] = __uint_as_float(tf32_hi(v2));
            base[(d0+3)*2] = __uint_as_float(tf32_hi(v3));
        }
    }
}

/* ------------------------------------------------------------------ */
/* 3xTF32 mma flash attention, pre-packed tiles, cp.async dbl-buffer. */
#define KP4PITCH 66
#define VP2PITCH 36
#define PP2PITCH 36
#define BUFF 6592   /* floats per buffer: K 4224 + V 2304 + bias 64 */
#define SM_FLOATS (2*BUFF + 4*16*PP2PITCH*2)
#define SMEM_BYTES (SM_FLOATS * 4)

__global__ void __launch_bounds__(128, 2) attn_kernel() {
    extern __shared__ __align__(16) float dsm[];
    float2* PP2 = (float2*)(dsm + 2 * BUFF);
    u32 sb = smem_u32(dsm);

    int tid = threadIdx.x, w = tid >> 5, lane = tid & 31;
    int g = lane >> 2, tq = lane & 3;
    int q0 = blockIdx.x * 128, hh = blockIdx.y, nn = blockIdx.z;
    const float* Qg = g_Qh + (size_t)(nn * NH + hh) * T * D;
    size_t hb4 = (size_t)(nn * NH + hh) * 32 * 1024;
    float2* Pw2 = PP2 + w * 16 * PP2PITCH;

    /* Q fragments (loop-invariant) */
    u32 qh[2][4][4], ql[2][4][4];
    #pragma unroll
    for (int m = 0; m < 2; ++m) {
        int r0 = (q0 + 32 * w + 16 * m + g) * D;
        int r1 = r0 + 8 * D;
        #pragma unroll
        for (int ks = 0; ks < 4; ++ks) {
            tf32_split(Qg[r0 + 8*ks + tq],     qh[m][ks][0], ql[m][ks][0]);
            tf32_split(Qg[r1 + 8*ks + tq],     qh[m][ks][1], ql[m][ks][1]);
            tf32_split(Qg[r0 + 8*ks + tq + 4], qh[m][ks][2], ql[m][ks][2]);
            tf32_split(Qg[r1 + 8*ks + tq + 4], qh[m][ks][3], ql[m][ks][3]);
        }
    }
    float O[2][4][4];
    #pragma unroll
    for (int m = 0; m < 2; ++m)
        #pragma unroll
        for (int nf = 0; nf < 4; ++nf)
            #pragma unroll
            for (int c = 0; c < 4; ++c) O[m][nf][c] = 0.0f;
    float mrun[2][2] = {{-1e30f,-1e30f},{-1e30f,-1e30f}};
    float lrun[2][2] = {{0.f,0.f},{0.f,0.f}};

    auto prefetch = [&](int kt, int buf) {
        u32 kb = sb + buf * (BUFF * 4);
        const float4* gk = g_Kp + hb4 + (size_t)kt * 1024;
        #pragma unroll
        for (int i = 0; i < 8; ++i) {
            int c = tid + i * 128;
            cpa16(kb + (c >> 6) * (KP4PITCH*16) + (c & 63) * 16, gk + c);
        }
        const float2* gv = g_Vp + hb4 + (size_t)kt * 1024;
        u32 vb = kb + 4224 * 4;
        #pragma unroll
        for (int i = 0; i < 4; ++i) {
            int c = tid + i * 128;
            cpa16(vb + (c >> 4) * (VP2PITCH*8) + (c & 15) * 16,
                  gv + (c >> 4) * 32 + (c & 15) * 2);
        }
        if (tid < 16)
            cpa16(kb + 6528 * 4 + tid * 16, g_kbias + nn * T + kt * 64 + tid * 4);
        CPA_COMMIT();
    };

    prefetch(0, 0);

    for (int kt = 0; kt < T / 64; ++kt) {
        int cur = kt & 1;
        int k0 = kt * 64;
        if (kt < T / 64 - 1) { prefetch(kt + 1, cur ^ 1); CPA_WAIT1(); }
        else CPA_WAIT0();
        __syncthreads();

        float4* KP4 = (float4*)(dsm + cur * BUFF);
        float2* VP2 = (float2*)(dsm + cur * BUFF + 4224);
        float*  bias_s = dsm + cur * BUFF + 6528;

        #pragma unroll
        for (int h = 0; h < 2; ++h) {
            /* ---- S = Q K^T (3xTF32) ---- */
            float s[2][4][4];
            #pragma unroll
            for (int m = 0; m < 2; ++m)
                #pragma unroll
                for (int j = 0; j < 4; ++j)
                    #pragma unroll
                    for (int c = 0; c < 4; ++c) s[m][j][c] = 0.0f;
            #pragma unroll
            for (int ks = 0; ks < 4; ++ks) {
                float4 kf[4];
                #pragma unroll
                for (int j = 0; j < 4; ++j)
                    kf[j] = KP4[(4*ks + tq) * KP4PITCH + 32*h + 8*j + g];
                #pragma unroll
                for (int m = 0; m < 2; ++m)
                    #pragma unroll
                    for (int j = 0; j < 4; ++j) {
                        u32 bh0 = __float_as_uint(kf[j].x);
                        u32 bh1 = __float_as_uint(kf[j].y);
                        u32 bl0 = __float_as_uint(kf[j].z);
                        u32 bl1 = __float_as_uint(kf[j].w);
                        MMA(s[m][j], qh[m][ks], bh0, bh1);
                        MMA(s[m][j], ql[m][ks], bh0, bh1);
                        MMA(s[m][j], qh[m][ks], bl0, bl1);
                    }
            }

            /* ---- softmax ---- */
            float2 bb[4];
            #pragma unroll
            for (int j = 0; j < 4; ++j)
                bb[j] = *(float2*)&bias_s[32 * h + 8 * j + 2 * tq];
            #pragma unroll
            for (int m = 0; m < 2; ++m)
                #pragma unroll
                for (int rg = 0; rg < 2; ++rg) {
                    float zv[8];
                    #pragma unroll
                    for (int j = 0; j < 4; ++j) {
                        zv[2*j]   = fmaf(s[m][j][2*rg],   SCALE, bb[j].x);
                        zv[2*j+1] = fmaf(s[m][j][2*rg+1], SCALE, bb[j].y);
                    }
                    float mx = zv[0];
                    #pragma unroll
                    for (int e = 1; e < 8; ++e) mx = fmaxf(mx, zv[e]);
                    mx = fmaxf(mx, __shfl_xor_sync(0xffffffffu, mx, 1));
                    mx = fmaxf(mx, __shfl_xor_sync(0xffffffffu, mx, 2));
                    float mn = fmaxf(mrun[m][rg], mx);
                    float fr = __expf(mrun[m][rg] - mn);
                    mrun[m][rg] = mn;
                    float sum = 0.0f;
                    #pragma unroll
                    for (int j = 0; j < 4; ++j) {
                        float p0 = __expf(zv[2*j]   - mn);
                        float p1 = __expf(zv[2*j+1] - mn);
                        sum += p0 + p1;
                        s[m][j][2*rg] = p0; s[m][j][2*rg+1] = p1;
                    }
                    sum += __shfl_xor_sync(0xffffffffu, sum, 1);
                    sum += __shfl_xor_sync(0xffffffffu, sum, 2);
                    lrun[m][rg] = lrun[m][rg] * fr + sum;
                    #pragma unroll
                    for (int nf = 0; nf < 4; ++nf) {
                        O[m][nf][2*rg]   *= fr;
                        O[m][nf][2*rg+1] *= fr;
                    }
                }

            /* ---- P -> paired smem ---- */
            __syncwarp();
            int kb = k0 + 32 * h + 2 * tq;
            #pragma unroll
            for (int m = 0; m < 2; ++m)
                #pragma unroll
                for (int j = 0; j < 4; ++j) {
                    float p1 = s[m][j][1], p3 = s[m][j][3];
                    if (kb + 8*j + 1 == T - 1) { p1 = 0.0f; p3 = 0.0f; }
                    float4 pv;
                    pv.x = s[m][j][0]; pv.y = s[m][j][2];
                    pv.z = p1;         pv.w = p3;
                    *(float4*)&Pw2[(8*m + g) * PP2PITCH + 8*j + 2*tq] = pv;
                }
            __syncwarp();

            /* ---- O += P V (2-term) ---- */
            #pragma unroll
            for (int ks = 0; ks < 4; ++ks) {
                u32 ph[2][4], pl[2][4];
                #pragma unroll
                for (int m = 0; m < 2; ++m) {
                    float2 pa = Pw2[(8*m + g) * PP2PITCH + 8*ks + tq];
                    float2 pb = Pw2[(8*m + g) * PP2PITCH + 8*ks + tq + 4];
                    tf32_split(pa.x, ph[m][0], pl[m][0]);
                    tf32_split(pa.y, ph[m][1], pl[m][1]);
                    tf32_split(pb.x, ph[m][2], pl[m][2]);
                    tf32_split(pb.y, ph[m][3], pl[m][3]);
                }
                #pragma unroll
                for (int nf = 0; nf < 4; ++nf) {
                    float2 vv = VP2[(16*h + 4*ks + tq) * VP2PITCH + 8*nf + g];
                    u32 vh0 = __float_as_uint(vv.x);
                    u32 vh1 = __float_as_uint(vv.y);
                    #pragma unroll
                    for (int m = 0; m < 2; ++m) {
                        MMA(O[m][nf], ph[m], vh0, vh1);
                        MMA(O[m][nf], pl[m], vh0, vh1);
                    }
                }
            }
        }
        __syncthreads();
    }

    /* ---- epilogue ---- */
    #pragma unroll
    for (int m = 0; m < 2; ++m)
        #pragma unroll
        for (int rg = 0; rg < 2; ++rg) {
            int row = q0 + 32 * w + 16 * m + 8 * rg + g;
            float inv = g_qmask[nn * T + row] / lrun[m][rg];
            float* dst = &g_ctx[(size_t)(nn * T + row) * H + hh * D];
            #pragma unroll
            for (int nf = 0; nf < 4; ++nf)
                *(float2*)&dst[8*nf + 2*tq] =
                    make_float2(O[m][nf][2*rg] * inv, O[m][nf][2*rg+1] * inv);
        }
}

/* ------------------------------------------------------------------ */
__global__ void __launch_bounds__(256) ln_kernel(
        const float* __restrict__ gamma, const float* __restrict__ beta,
        float* __restrict__ out, float* __restrict__ wout) {
    int row = blockIdx.x, t = threadIdx.x;
    float x = g_ctx[(size_t)row * H + t];
    __shared__ float rs[8], rq[8];
    float s = x, q = x * x;
    #pragma unroll
    for (int o = 16; o; o >>= 1) {
        s += __shfl_xor_sync(0xffffffffu, s, o);
        q += __shfl_xor_sync(0xffffffffu, q, o);
    }
    if ((t & 31) == 0) { rs[t >> 5] = s; rq[t >> 5] = q; }
    __syncthreads();
    float ts = 0.0f, tq = 0.0f;
    #pragma unroll
    for (int i = 0; i < 8; ++i) { ts += rs[i]; tq += rq[i]; }
    float mu = ts * (1.0f / H);
    float var = tq * (1.0f / H) - mu * mu;
    float inv = rsqrtf(var + 1e-5f);
    out[(size_t)row * H + t] = (x - mu) * inv * gamma[t] + beta[t];
    if (t == 0) wout[row] = g_qmask[row] * (1.0f / (float)T);
}

/* ------------------------------------------------------------------ */
extern "C" void kernel_launch(void* const* d_in, const int* in_sizes, int n_in,
                              void* d_out, int out_size) {
    const float* Q  = (const float*)d_in[0];
    const float* K  = (const float*)d_in[1];
    const float* V  = (const float*)d_in[2];
    const float* Wq = (const float*)d_in[3];
    const float* bq = (const float*)d_in[4];
    const float* Wk = (const float*)d_in[5];
    const float* bk = (const float*)d_in[6];
    const float* Wv = (const float*)d_in[7];
    const float* bv = (const float*)d_in[8];
    const float* gamma = (const float*)d_in[9];
    const float* beta  = (const float*)d_in[10];

    float* out  = (float*)d_out;
    float* wout = out + (out_size - Nb * T);

    cudaFuncSetAttribute(attn_kernel,
                         cudaFuncAttributeMaxDynamicSharedMemorySize, SMEM_BYTES);

    mask_kernel<<<dim3(Nb * T, 2), 128>>>(Q, K);
    proj_kernel<<<dim3(H / 64, (Nb * T) / 64, 3), 256>>>(Q, K, V,
                                                         Wq, Wk, Wv,
                                                         bq, bk, bv);
    attn_kernel<<<dim3(T / 128, NH, Nb), 128, SMEM_BYTES>>>();
    ln_kernel<<<Nb * T, 256>>>(gamma, beta, out, wout);
}

// round 11
// speedup vs baseline: 1.3560x; 1.0099x over previous
#include <cuda_runtime.h>
#include <cstdint>
#include <math.h>

#define Nb 2
#define T  2048
#define H  256
#define NH 8
#define D  32
#define SCALE 17.677669529663689f

typedef unsigned long long u64;
typedef uint32_t u32;

__device__ __forceinline__ void fma2(u64& d, u64 a, u64 b) {
    asm("fma.rn.f32x2 %0, %1, %2, %0;" : "+l"(d) : "l"(a), "l"(b));
}
__device__ __forceinline__ u64 pack2(float x, float y) {
    u64 r; asm("mov.b64 %0, {%1, %2};" : "=l"(r) : "f"(x), "f"(y)); return r;
}
__device__ __forceinline__ float2 unpack2(u64 v) {
    float2 f; asm("mov.b64 {%0, %1}, %2;" : "=f"(f.x), "=f"(f.y) : "l"(v)); return f;
}
__device__ __forceinline__ u32 tf32_hi(float x) {
    u32 h; asm("cvt.rna.tf32.f32 %0, %1;" : "=r"(h) : "f"(x)); return h;
}
__device__ __forceinline__ void tf32_split(float x, u32& hi, u32& lo) {
    hi = tf32_hi(x);
    lo = tf32_hi(x - __uint_as_float(hi));
}
__device__ __forceinline__ u32 smem_u32(const void* p) {
    u32 a;
    asm("{ .reg .u64 t; cvta.to.shared.u64 t, %1; cvt.u32.u64 %0, t; }" : "=r"(a) : "l"(p));
    return a;
}
__device__ __forceinline__ void cpa16(u32 saddr, const void* g) {
    asm volatile("cp.async.cg.shared.global [%0], [%1], 16;" :: "r"(saddr), "l"(g));
}
#define CPA_COMMIT() asm volatile("cp.async.commit_group;" ::: "memory")
#define CPA_WAIT1()  asm volatile("cp.async.wait_group 1;"  ::: "memory")
#define CPA_WAIT0()  asm volatile("cp.async.wait_group 0;"  ::: "memory")
#define MMA(c, a, b0, b1) \
    asm volatile("mma.sync.aligned.m16n8k8.row.col.f32.tf32.tf32.f32 " \
        "{%0,%1,%2,%3}, {%4,%5,%6,%7}, {%8,%9}, {%0,%1,%2,%3};" \
        : "+f"((c)[0]), "+f"((c)[1]), "+f"((c)[2]), "+f"((c)[3]) \
        : "r"((a)[0]), "r"((a)[1]), "r"((a)[2]), "r"((a)[3]), "r"(b0), "r"(b1))

__device__ __align__(16) float g_Qh[Nb*NH*T*D];        /* [n][h][t][d] fp32 */
__device__ __align__(16) float4 g_Kp[Nb*NH*32*1024];   /* packed K tiles    */
__device__ __align__(16) float2 g_Vp[Nb*NH*32*1024];   /* packed V tiles    */
__device__ __align__(16) float g_ctx[Nb*T*H];
__device__ float g_kbias[Nb*T];   /* 0 or -1e35 */
__device__ float g_qmask[Nb*T];

/* ------------------------------------------------------------------ */
__global__ void mask_kernel(const float* __restrict__ Q,
                            const float* __restrict__ K) {
    int row = blockIdx.x;
    const float* src = blockIdx.y ? K : Q;
    int t = threadIdx.x;
    float s = fabsf(src[row*H + t]) + fabsf(src[row*H + t + 128]);
    __shared__ float red[4];
    #pragma unroll
    for (int o = 16; o; o >>= 1) s += __shfl_xor_sync(0xffffffffu, s, o);
    if ((t & 31) == 0) red[t >> 5] = s;
    __syncthreads();
    if (t == 0) {
        float tot = red[0] + red[1] + red[2] + red[3];
        if (blockIdx.y) g_kbias[row] = (tot != 0.0f) ? 0.0f : -1e35f;
        else            g_qmask[row] = (tot != 0.0f) ? 1.0f : 0.0f;
    }
}

/* ------------------------------------------------------------------ */
__global__ void __launch_bounds__(256) proj_kernel(
        const float* __restrict__ Q, const float* __restrict__ K,
        const float* __restrict__ V,
        const float* __restrict__ Wq, const float* __restrict__ Wk,
        const float* __restrict__ Wv,
        const float* __restrict__ bq, const float* __restrict__ bk,
        const float* __restrict__ bv) {
    int sel = blockIdx.z;
    const float* X = (sel == 0) ? Q  : (sel == 1) ? K  : V;
    const float* W = (sel == 0) ? Wq : (sel == 1) ? Wk : Wv;
    const float* b = (sel == 0) ? bq : (sel == 1) ? bk : bv;
    int m0 = blockIdx.y * 64, n0 = blockIdx.x * 64;
    __shared__ __align__(16) float Xst[32][68];
    __shared__ __align__(16) float Wsh[32][68];
    int tid = threadIdx.x, ty = tid >> 4, tx = tid & 15;
    u64 acc2[4][2] = {};
    for (int k0 = 0; k0 < H; k0 += 32) {
        __syncthreads();
        #pragma unroll
        for (int it = 0; it < 8; ++it) {
            int e = tid + it * 256;
            int r = e >> 5, c = e & 31;
            Xst[c][r] = X[(m0 + r) * H + k0 + c];
            int r2 = e >> 6, c2 = e & 63;
            Wsh[r2][c2] = W[(k0 + r2) * H + n0 + c2];
        }
        __syncthreads();
        #pragma unroll
        for (int kk = 0; kk < 32; ++kk) {
            float4 a = *(const float4*)&Xst[kk][4 * ty];
            ulonglong2 bb = *(const ulonglong2*)&Wsh[kk][4 * tx];
            u64 a0 = pack2(a.x, a.x), a1 = pack2(a.y, a.y);
            u64 a2 = pack2(a.z, a.z), a3 = pack2(a.w, a.w);
            fma2(acc2[0][0], a0, bb.x); fma2(acc2[0][1], a0, bb.y);
            fma2(acc2[1][0], a1, bb.x); fma2(acc2[1][1], a1, bb.y);
            fma2(acc2[2][0], a2, bb.x); fma2(acc2[2][1], a2, bb.y);
            fma2(acc2[3][0], a3, bb.x); fma2(acc2[3][1], a3, bb.y);
        }
    }
    int c0 = n0 + 4 * tx, hh = c0 >> 5, d0 = c0 & 31;
    float b0 = b[c0+0], b1 = b[c0+1], b2 = b[c0+2], b3 = b[c0+3];
    #pragma unroll
    for (int i = 0; i < 4; ++i) {
        int m = m0 + 4 * ty + i, nn = m >> 11, tt = m & 2047;
        float2 lo = unpack2(acc2[i][0]), hi = unpack2(acc2[i][1]);
        float v0 = fmaxf(lo.x + b0, 0.0f), v1 = fmaxf(lo.y + b1, 0.0f);
        float v2 = fmaxf(hi.x + b2, 0.0f), v3 = fmaxf(hi.y + b3, 0.0f);
        int tile = tt >> 6;
        size_t tbase = ((size_t)(nn * NH + hh) * 32 + tile) * 1024;
        if (sel == 0) {
            *(float4*)&g_Qh[(((size_t)(nn * NH) + hh) * T + tt) * D + d0] =
                make_float4(v0, v1, v2, v3);
        } else if (sel == 1) {
            int key = tt & 63;
            int q = d0 >> 3, sl = (d0 & 4) ? 1 : 0;
            u32 hb[4], lb[4];
            tf32_split(v0, hb[0], lb[0]); tf32_split(v1, hb[1], lb[1]);
            tf32_split(v2, hb[2], lb[2]); tf32_split(v3, hb[3], lb[3]);
            float* base = (float*)g_Kp + (tbase + key) * 4;
            #pragma unroll
            for (int j = 0; j < 4; ++j) {
                base[((4*q + j) * 64) * 4 + sl]     = __uint_as_float(hb[j]);
                base[((4*q + j) * 64) * 4 + sl + 2] = __uint_as_float(lb[j]);
            }
        } else {
            int rr = tt & 63;
            int q = rr >> 3, rm = rr & 7, kgrp = 4*q + (rm & 3), sl = rm >> 2;
            float* base = (float*)g_Vp + (tbase + kgrp * 32) * 2 + sl;
            base[(d0+0)*2] = __uint_as_float(tf32_hi(v0));
            base[(d0+1)*2] = __uint_as_float(tf32_hi(v1));
            base[(d0+2)*2] = __uint_as_float(tf32_hi(v2));
            base[(d0+3)*2] = __uint_as_float(tf32_hi(v3));
        }
    }
}

/* ------------------------------------------------------------------ */
/* 3xTF32 mma flash attention; S for both half-tiles batched ahead of */
/* softmax/PV so tensor work overlaps the softmax latency chain.      */
#define KP4PITCH 66
#define VP2PITCH 36
#define PP2PITCH 36
#define BUFF 6592   /* floats per buffer: K 4224 + V 2304 + bias 64 */
#define SM_FLOATS (2*BUFF + 4*16*PP2PITCH*2)
#define SMEM_BYTES (SM_FLOATS * 4)

__global__ void __launch_bounds__(128, 2) attn_kernel() {
    extern __shared__ __align__(16) float dsm[];
    float2* PP2 = (float2*)(dsm + 2 * BUFF);
    u32 sb = smem_u32(dsm);

    int tid = threadIdx.x, w = tid >> 5, lane = tid & 31;
    int g = lane >> 2, tq = lane & 3;
    int q0 = blockIdx.x * 128, hh = blockIdx.y, nn = blockIdx.z;
    const float* Qg = g_Qh + (size_t)(nn * NH + hh) * T * D;
    size_t hb4 = (size_t)(nn * NH + hh) * 32 * 1024;
    float2* Pw2 = PP2 + w * 16 * PP2PITCH;

    /* Q fragments (loop-invariant) */
    u32 qh[2][4][4], ql[2][4][4];
    #pragma unroll
    for (int m = 0; m < 2; ++m) {
        int r0 = (q0 + 32 * w + 16 * m + g) * D;
        int r1 = r0 + 8 * D;
        #pragma unroll
        for (int ks = 0; ks < 4; ++ks) {
            tf32_split(Qg[r0 + 8*ks + tq],     qh[m][ks][0], ql[m][ks][0]);
            tf32_split(Qg[r1 + 8*ks + tq],     qh[m][ks][1], ql[m][ks][1]);
            tf32_split(Qg[r0 + 8*ks + tq + 4], qh[m][ks][2], ql[m][ks][2]);
            tf32_split(Qg[r1 + 8*ks + tq + 4], qh[m][ks][3], ql[m][ks][3]);
        }
    }
    float O[2][4][4];
    #pragma unroll
    for (int m = 0; m < 2; ++m)
        #pragma unroll
        for (int nf = 0; nf < 4; ++nf)
            #pragma unroll
            for (int c = 0; c < 4; ++c) O[m][nf][c] = 0.0f;
    float mrun[2][2] = {{-1e30f,-1e30f},{-1e30f,-1e30f}};
    float lrun[2][2] = {{0.f,0.f},{0.f,0.f}};

    auto prefetch = [&](int kt, int buf) {
        u32 kb = sb + buf * (BUFF * 4);
        const float4* gk = g_Kp + hb4 + (size_t)kt * 1024;
        #pragma unroll
        for (int i = 0; i < 8; ++i) {
            int c = tid + i * 128;
            cpa16(kb + (c >> 6) * (KP4PITCH*16) + (c & 63) * 16, gk + c);
        }
        const float2* gv = g_Vp + hb4 + (size_t)kt * 1024;
        u32 vb = kb + 4224 * 4;
        #pragma unroll
        for (int i = 0; i < 4; ++i) {
            int c = tid + i * 128;
            cpa16(vb + (c >> 4) * (VP2PITCH*8) + (c & 15) * 16,
                  gv + (c >> 4) * 32 + (c & 15) * 2);
        }
        if (tid < 16)
            cpa16(kb + 6528 * 4 + tid * 16, g_kbias + nn * T + kt * 64 + tid * 4);
        CPA_COMMIT();
    };

    prefetch(0, 0);

    for (int kt = 0; kt < T / 64; ++kt) {
        int cur = kt & 1;
        int k0 = kt * 64;
        if (kt < T / 64 - 1) { prefetch(kt + 1, cur ^ 1); CPA_WAIT1(); }
        else CPA_WAIT0();
        __syncthreads();

        float4* KP4 = (float4*)(dsm + cur * BUFF);
        float2* VP2 = (float2*)(dsm + cur * BUFF + 4224);
        float*  bias_s = dsm + cur * BUFF + 6528;

        /* ---- S = Q K^T for BOTH halves (tensor work batched) ---- */
        float s[2][2][4][4];
        #pragma unroll
        for (int h = 0; h < 2; ++h)
            #pragma unroll
            for (int m = 0; m < 2; ++m)
                #pragma unroll
                for (int j = 0; j < 4; ++j)
                    #pragma unroll
                    for (int c = 0; c < 4; ++c) s[h][m][j][c] = 0.0f;
        #pragma unroll
        for (int ks = 0; ks < 4; ++ks) {
            #pragma unroll
            for (int h = 0; h < 2; ++h) {
                float4 kf[4];
                #pragma unroll
                for (int j = 0; j < 4; ++j)
                    kf[j] = KP4[(4*ks + tq) * KP4PITCH + 32*h + 8*j + g];
                #pragma unroll
                for (int m = 0; m < 2; ++m)
                    #pragma unroll
                    for (int j = 0; j < 4; ++j) {
                        u32 bh0 = __float_as_uint(kf[j].x);
                        u32 bh1 = __float_as_uint(kf[j].y);
                        u32 bl0 = __float_as_uint(kf[j].z);
                        u32 bl1 = __float_as_uint(kf[j].w);
                        MMA(s[h][m][j], qh[m][ks], bh0, bh1);
                        MMA(s[h][m][j], ql[m][ks], bh0, bh1);
                        MMA(s[h][m][j], qh[m][ks], bl0, bl1);
                    }
            }
        }

        /* ---- per half: softmax, P store, PV ---- */
        #pragma unroll
        for (int h = 0; h < 2; ++h) {
            float (*sh)[4][4] = s[h];
            float2 bb[4];
            #pragma unroll
            for (int j = 0; j < 4; ++j)
                bb[j] = *(float2*)&bias_s[32 * h + 8 * j + 2 * tq];
            #pragma unroll
            for (int m = 0; m < 2; ++m)
                #pragma unroll
                for (int rg = 0; rg < 2; ++rg) {
                    float zv[8];
                    #pragma unroll
                    for (int j = 0; j < 4; ++j) {
                        zv[2*j]   = fmaf(sh[m][j][2*rg],   SCALE, bb[j].x);
                        zv[2*j+1] = fmaf(sh[m][j][2*rg+1], SCALE, bb[j].y);
                    }
                    float mx = zv[0];
                    #pragma unroll
                    for (int e = 1; e < 8; ++e) mx = fmaxf(mx, zv[e]);
                    mx = fmaxf(mx, __shfl_xor_sync(0xffffffffu, mx, 1));
                    mx = fmaxf(mx, __shfl_xor_sync(0xffffffffu, mx, 2));
                    float mn = fmaxf(mrun[m][rg], mx);
                    float fr = __expf(mrun[m][rg] - mn);
                    mrun[m][rg] = mn;
                    float sum = 0.0f;
                    #pragma unroll
                    for (int j = 0; j < 4; ++j) {
                        float p0 = __expf(zv[2*j]   - mn);
                        float p1 = __expf(zv[2*j+1] - mn);
                        sum += p0 + p1;
                        sh[m][j][2*rg] = p0; sh[m][j][2*rg+1] = p1;
                    }
                    sum += __shfl_xor_sync(0xffffffffu, sum, 1);
                    sum += __shfl_xor_sync(0xffffffffu, sum, 2);
                    lrun[m][rg] = lrun[m][rg] * fr + sum;
                    #pragma unroll
                    for (int nf = 0; nf < 4; ++nf) {
                        O[m][nf][2*rg]   *= fr;
                        O[m][nf][2*rg+1] *= fr;
                    }
                }

            /* P -> paired smem */
            __syncwarp();
            int kb = k0 + 32 * h + 2 * tq;
            #pragma unroll
            for (int m = 0; m < 2; ++m)
                #pragma unroll
                for (int j = 0; j < 4; ++j) {
                    float p1 = sh[m][j][1], p3 = sh[m][j][3];
                    if (kb + 8*j + 1 == T - 1) { p1 = 0.0f; p3 = 0.0f; }
                    float4 pv;
                    pv.x = sh[m][j][0]; pv.y = sh[m][j][2];
                    pv.z = p1;          pv.w = p3;
                    *(float4*)&Pw2[(8*m + g) * PP2PITCH + 8*j + 2*tq] = pv;
                }
            __syncwarp();

            /* O += P V (2-term) */
            #pragma unroll
            for (int ks = 0; ks < 4; ++ks) {
                u32 ph[2][4], pl[2][4];
                #pragma unroll
                for (int m = 0; m < 2; ++m) {
                    float2 pa = Pw2[(8*m + g) * PP2PITCH + 8*ks + tq];
                    float2 pb = Pw2[(8*m + g) * PP2PITCH + 8*ks + tq + 4];
                    tf32_split(pa.x, ph[m][0], pl[m][0]);
                    tf32_split(pa.y, ph[m][1], pl[m][1]);
                    tf32_split(pb.x, ph[m][2], pl[m][2]);
                    tf32_split(pb.y, ph[m][3], pl[m][3]);
                }
                #pragma unroll
                for (int nf = 0; nf < 4; ++nf) {
                    float2 vv = VP2[(16*h + 4*ks + tq) * VP2PITCH + 8*nf + g];
                    u32 vh0 = __float_as_uint(vv.x);
                    u32 vh1 = __float_as_uint(vv.y);
                    #pragma unroll
                    for (int m = 0; m < 2; ++m) {
                        MMA(O[m][nf], ph[m], vh0, vh1);
                        MMA(O[m][nf], pl[m], vh0, vh1);
                    }
                }
            }
        }
        __syncthreads();
    }

    /* ---- epilogue ---- */
    #pragma unroll
    for (int m = 0; m < 2; ++m)
        #pragma unroll
        for (int rg = 0; rg < 2; ++rg) {
            int row = q0 + 32 * w + 16 * m + 8 * rg + g;
            float inv = g_qmask[nn * T + row] / lrun[m][rg];
            float* dst = &g_ctx[(size_t)(nn * T + row) * H + hh * D];
            #pragma unroll
            for (int nf = 0; nf < 4; ++nf)
                *(float2*)&dst[8*nf + 2*tq] =
                    make_float2(O[m][nf][2*rg] * inv, O[m][nf][2*rg+1] * inv);
        }
}

/* ------------------------------------------------------------------ */
__global__ void __launch_bounds__(256) ln_kernel(
        const float* __restrict__ gamma, const float* __restrict__ beta,
        float* __restrict__ out, float* __restrict__ wout) {
    int row = blockIdx.x, t = threadIdx.x;
    float x = g_ctx[(size_t)row * H + t];
    __shared__ float rs[8], rq[8];
    float s = x, q = x * x;
    #pragma unroll
    for (int o = 16; o; o >>= 1) {
        s += __shfl_xor_sync(0xffffffffu, s, o);
        q += __shfl_xor_sync(0xffffffffu, q, o);
    }
    if ((t & 31) == 0) { rs[t >> 5] = s; rq[t >> 5] = q; }
    __syncthreads();
    float ts = 0.0f, tq = 0.0f;
    #pragma unroll
    for (int i = 0; i < 8; ++i) { ts += rs[i]; tq += rq[i]; }
    float mu = ts * (1.0f / H);
    float var = tq * (1.0f / H) - mu * mu;
    float inv = rsqrtf(var + 1e-5f);
    out[(size_t)row * H + t] = (x - mu) * inv * gamma[t] + beta[t];
    if (t == 0) wout[row] = g_qmask[row] * (1.0f / (float)T);
}

/* ------------------------------------------------------------------ */
extern "C" void kernel_launch(void* const* d_in, const int* in_sizes, int n_in,
                              void* d_out, int out_size) {
    const float* Q  = (const float*)d_in[0];
    const float* K  = (const float*)d_in[1];
    const float* V  = (const float*)d_in[2];
    const float* Wq = (const float*)d_in[3];
    const float* bq = (const float*)d_in[4];
    const float* Wk = (const float*)d_in[5];
    const float* bk = (const float*)d_in[6];
    const float* Wv = (const float*)d_in[7];
    const float* bv = (const float*)d_in[8];
    const float* gamma = (const float*)d_in[9];
    const float* beta  = (const float*)d_in[10];

    float* out  = (float*)d_out;
    float* wout = out + (out_size - Nb * T);

    cudaFuncSetAttribute(attn_kernel,
                         cudaFuncAttributeMaxDynamicSharedMemorySize, SMEM_BYTES);

    mask_kernel<<<dim3(Nb * T, 2), 128>>>(Q, K);
    proj_kernel<<<dim3(H / 64, (Nb * T) / 64, 3), 256>>>(Q, K, V,
                                                         Wq, Wk, Wv,
                                                         bq, bk, bv);
    attn_kernel<<<dim3(T / 128, NH, Nb), 128, SMEM_BYTES>>>();
    ln_kernel<<<Nb * T, 256>>>(gamma, beta, out, wout);
}

// round 12
// speedup vs baseline: 1.8636x; 1.3743x over previous
#include <cuda_runtime.h>
#include <cstdint>
#include <math.h>

#define Nb 2
#define T  2048
#define H  256
#define NH 8
#define D  32
#define SCALE 17.677669529663689f

typedef unsigned long long u64;
typedef uint32_t u32;

__device__ __forceinline__ void fma2(u64& d, u64 a, u64 b) {
    asm("fma.rn.f32x2 %0, %1, %2, %0;" : "+l"(d) : "l"(a), "l"(b));
}
__device__ __forceinline__ u64 pack2(float x, float y) {
    u64 r; asm("mov.b64 %0, {%1, %2};" : "=l"(r) : "f"(x), "f"(y)); return r;
}
__device__ __forceinline__ float2 unpack2(u64 v) {
    float2 f; asm("mov.b64 {%0, %1}, %2;" : "=f"(f.x), "=f"(f.y) : "l"(v)); return f;
}
__device__ __forceinline__ u32 f16pack(float lo, float hi) {
    u32 r; asm("cvt.rn.f16x2.f32 %0, %1, %2;" : "=r"(r) : "f"(hi), "f"(lo)); return r;
}
/* hi/lo fp16 split of (x,y): hp + lp reconstructs to ~2^-22 */
__device__ __forceinline__ void f16split2(float x, float y, u32& hp, u32& lp) {
    hp = f16pack(x, y);
    float hx, hy;
    asm("{.reg .f16 l,h; mov.b32 {l,h}, %2; cvt.f32.f16 %0, l; cvt.f32.f16 %1, h;}"
        : "=f"(hx), "=f"(hy) : "r"(hp));
    lp = f16pack(x - hx, y - hy);
}
__device__ __forceinline__ u32 smem_u32(const void* p) {
    u32 a;
    asm("{ .reg .u64 t; cvta.to.shared.u64 t, %1; cvt.u32.u64 %0, t; }" : "=r"(a) : "l"(p));
    return a;
}
__device__ __forceinline__ void cpa16(u32 saddr, const void* g) {
    asm volatile("cp.async.cg.shared.global [%0], [%1], 16;" :: "r"(saddr), "l"(g));
}
#define CPA_COMMIT() asm volatile("cp.async.commit_group;" ::: "memory")
#define CPA_WAIT1()  asm volatile("cp.async.wait_group 1;"  ::: "memory")
#define CPA_WAIT0()  asm volatile("cp.async.wait_group 0;"  ::: "memory")
#define MMA16(c, a, b0, b1) \
    asm volatile("mma.sync.aligned.m16n8k16.row.col.f32.f16.f16.f32 " \
        "{%0,%1,%2,%3}, {%4,%5,%6,%7}, {%8,%9}, {%0,%1,%2,%3};" \
        : "+f"((c)[0]), "+f"((c)[1]), "+f"((c)[2]), "+f"((c)[3]) \
        : "r"((a)[0]), "r"((a)[1]), "r"((a)[2]), "r"((a)[3]), "r"(b0), "r"(b1))

/* packed K: [n*NH][32 tiles][8 grp][64 key] float4 {hi0,hi1,lo0,lo1} */
__device__ __align__(16) float4 g_Kp[Nb*NH*32*512];
/* packed V: [n*NH][32 tiles][16 grp][32 d] u64 {b0 f16x2, b1 f16x2}  */
__device__ __align__(16) u64 g_Vp[Nb*NH*32*512];
__device__ __align__(16) float g_Qh[Nb*NH*T*D];
__device__ __align__(16) float g_ctx[Nb*T*H];
__device__ float g_kbias[Nb*T];   /* 0 or -1e35 */
__device__ float g_qmask[Nb*T];

/* ------------------------------------------------------------------ */
__global__ void mask_kernel(const float* __restrict__ Q,
                            const float* __restrict__ K) {
    int row = blockIdx.x;
    const float* src = blockIdx.y ? K : Q;
    int t = threadIdx.x;
    float s = fabsf(src[row*H + t]) + fabsf(src[row*H + t + 128]);
    __shared__ float red[4];
    #pragma unroll
    for (int o = 16; o; o >>= 1) s += __shfl_xor_sync(0xffffffffu, s, o);
    if ((t & 31) == 0) red[t >> 5] = s;
    __syncthreads();
    if (t == 0) {
        float tot = red[0] + red[1] + red[2] + red[3];
        if (blockIdx.y) g_kbias[row] = (tot != 0.0f) ? 0.0f : -1e35f;
        else            g_qmask[row] = (tot != 0.0f) ? 1.0f : 0.0f;
    }
}

/* ------------------------------------------------------------------ */
__global__ void __launch_bounds__(256) proj_kernel(
        const float* __restrict__ Q, const float* __restrict__ K,
        const float* __restrict__ V,
        const float* __restrict__ Wq, const float* __restrict__ Wk,
        const float* __restrict__ Wv,
        const float* __restrict__ bq, const float* __restrict__ bk,
        const float* __restrict__ bv) {
    int sel = blockIdx.z;
    const float* X = (sel == 0) ? Q  : (sel == 1) ? K  : V;
    const float* W = (sel == 0) ? Wq : (sel == 1) ? Wk : Wv;
    const float* b = (sel == 0) ? bq : (sel == 1) ? bk : bv;
    int m0 = blockIdx.y * 64, n0 = blockIdx.x * 64;
    __shared__ __align__(16) float Xst[32][68];
    __shared__ __align__(16) float Wsh[32][68];
    int tid = threadIdx.x, ty = tid >> 4, tx = tid & 15;
    u64 acc2[4][2] = {};
    for (int k0 = 0; k0 < H; k0 += 32) {
        __syncthreads();
        #pragma unroll
        for (int it = 0; it < 8; ++it) {
            int e = tid + it * 256;
            int r = e >> 5, c = e & 31;
            Xst[c][r] = X[(m0 + r) * H + k0 + c];
            int r2 = e >> 6, c2 = e & 63;
            Wsh[r2][c2] = W[(k0 + r2) * H + n0 + c2];
        }
        __syncthreads();
        #pragma unroll
        for (int kk = 0; kk < 32; ++kk) {
            float4 a = *(const float4*)&Xst[kk][4 * ty];
            ulonglong2 bb = *(const ulonglong2*)&Wsh[kk][4 * tx];
            u64 a0 = pack2(a.x, a.x), a1 = pack2(a.y, a.y);
            u64 a2 = pack2(a.z, a.z), a3 = pack2(a.w, a.w);
            fma2(acc2[0][0], a0, bb.x); fma2(acc2[0][1], a0, bb.y);
            fma2(acc2[1][0], a1, bb.x); fma2(acc2[1][1], a1, bb.y);
            fma2(acc2[2][0], a2, bb.x); fma2(acc2[2][1], a2, bb.y);
            fma2(acc2[3][0], a3, bb.x); fma2(acc2[3][1], a3, bb.y);
        }
    }
    int c0 = n0 + 4 * tx, hh = c0 >> 5, d0 = c0 & 31;
    float b0 = b[c0+0], b1 = b[c0+1], b2 = b[c0+2], b3 = b[c0+3];
    #pragma unroll
    for (int i = 0; i < 4; ++i) {
        int m = m0 + 4 * ty + i, nn = m >> 11, tt = m & 2047;
        float2 lo = unpack2(acc2[i][0]), hi = unpack2(acc2[i][1]);
        float v0 = fmaxf(lo.x + b0, 0.0f), v1 = fmaxf(lo.y + b1, 0.0f);
        float v2 = fmaxf(hi.x + b2, 0.0f), v3 = fmaxf(hi.y + b3, 0.0f);
        int tile = tt >> 6, kk = tt & 63;
        size_t tbase = ((size_t)(nn * NH + hh) * 32 + tile) * 512;
        if (sel == 0) {
            *(float4*)&g_Qh[(((size_t)(nn * NH) + hh) * T + tt) * D + d0] =
                make_float4(v0, v1, v2, v3);
        } else if (sel == 1) {
            /* K: dp0 = d0/2 (pair v0,v1), dp1 = dp0+1 (pair v2,v3) */
            u32 h0, l0, h1, l1;
            f16split2(v0, v1, h0, l0);
            f16split2(v2, v3, h1, l1);
            int dp0 = d0 >> 1;
            #pragma unroll
            for (int p = 0; p < 2; ++p) {
                int dp = dp0 + p;
                int ks = dp >> 3, r = dp & 7, sB = r >> 2, tq = r & 3;
                u32* dst = (u32*)&g_Kp[tbase + (4*ks + tq) * 64 + kk];
                dst[sB]     = p ? h1 : h0;
                dst[sB + 2] = p ? l1 : l0;
            }
        } else {
            /* V: key kk -> kp = kk/2, sl = kk&1; store 4 fp16 (one per d) */
            int kp = kk >> 1, sl = kk & 1;
            int r = kp & 7, sB = r >> 2, tq = r & 3, ks2 = kp >> 3;
            char* base = (char*)&g_Vp[tbase + ((4*ks2 + tq) * 32 + d0)]
                         + sB * 4 + sl * 2;
            unsigned short hv;
            asm("cvt.rn.f16.f32 %0, %1;" : "=h"(hv) : "f"(v0)); *(unsigned short*)(base)      = hv;
            asm("cvt.rn.f16.f32 %0, %1;" : "=h"(hv) : "f"(v1)); *(unsigned short*)(base + 8)  = hv;
            asm("cvt.rn.f16.f32 %0, %1;" : "=h"(hv) : "f"(v2)); *(unsigned short*)(base + 16) = hv;
            asm("cvt.rn.f16.f32 %0, %1;" : "=h"(hv) : "f"(v3)); *(unsigned short*)(base + 24) = hv;
        }
    }
}

/* ------------------------------------------------------------------ */
/* fp16-k16 3-term flash attention. Grid (16, NH, Nb), 128 thr.       */
/* smem/buffer: K 8x66 float4 (8448B) + V 16x36 u64 (4608B) + bias.   */
#define KOFF 0
#define VOFF 8448
#define BOFF 13056
#define BUFFB 13312
#define SMEM_BYTES (2 * BUFFB)

__global__ void __launch_bounds__(128, 3) attn_kernel() {
    extern __shared__ __align__(16) char dsm[];
    u32 sb = smem_u32(dsm);

    int tid = threadIdx.x, w = tid >> 5, lane = tid & 31;
    int g = lane >> 2, tq = lane & 3;
    int q0 = blockIdx.x * 128, hh = blockIdx.y, nn = blockIdx.z;
    const float* Qg = g_Qh + (size_t)(nn * NH + hh) * T * D;
    size_t tb = (size_t)(nn * NH + hh) * 32 * 512;

    /* Q fragments: a0:(g, d=16ks+2tq,+1) a1:(g+8) a2:(g, +8..9) a3:(g+8) */
    u32 qh[2][2][4], ql[2][2][4];
    #pragma unroll
    for (int m = 0; m < 2; ++m) {
        int r0 = (q0 + 32 * w + 16 * m + g) * D;
        int r1 = r0 + 8 * D;
        #pragma unroll
        for (int ks = 0; ks < 2; ++ks) {
            float2 xa = *(const float2*)&Qg[r0 + 16*ks + 2*tq];
            float2 xb = *(const float2*)&Qg[r1 + 16*ks + 2*tq];
            float2 xc = *(const float2*)&Qg[r0 + 16*ks + 2*tq + 8];
            float2 xd = *(const float2*)&Qg[r1 + 16*ks + 2*tq + 8];
            f16split2(xa.x, xa.y, qh[m][ks][0], ql[m][ks][0]);
            f16split2(xb.x, xb.y, qh[m][ks][1], ql[m][ks][1]);
            f16split2(xc.x, xc.y, qh[m][ks][2], ql[m][ks][2]);
            f16split2(xd.x, xd.y, qh[m][ks][3], ql[m][ks][3]);
        }
    }
    float O[2][4][4];
    #pragma unroll
    for (int m = 0; m < 2; ++m)
        #pragma unroll
        for (int nf = 0; nf < 4; ++nf)
            #pragma unroll
            for (int c = 0; c < 4; ++c) O[m][nf][c] = 0.0f;
    float mrun[2][2] = {{-1e30f,-1e30f},{-1e30f,-1e30f}};
    float lrun[2][2] = {{0.f,0.f},{0.f,0.f}};

    auto prefetch = [&](int kt, int buf) {
        u32 base = sb + buf * BUFFB;
        const float4* gk = g_Kp + tb + (size_t)kt * 512;
        #pragma unroll
        for (int i = 0; i < 4; ++i) {
            int c = tid + i * 128;
            cpa16(base + KOFF + (c >> 6) * (66*16) + (c & 63) * 16, gk + c);
        }
        const u64* gv = g_Vp + tb + (size_t)kt * 512;
        #pragma unroll
        for (int i = 0; i < 2; ++i) {
            int c = tid + i * 128;
            cpa16(base + VOFF + (c >> 4) * 288 + (c & 15) * 16, gv + c * 2);
        }
        if (tid < 16)
            cpa16(base + BOFF + tid * 16, g_kbias + nn * T + kt * 64 + tid * 4);
        CPA_COMMIT();
    };

    prefetch(0, 0);

    for (int kt = 0; kt < T / 64; ++kt) {
        int cur = kt & 1;
        if (kt < T / 64 - 1) { prefetch(kt + 1, cur ^ 1); CPA_WAIT1(); }
        else CPA_WAIT0();
        __syncthreads();

        const float4* KP4 = (const float4*)(dsm + cur * BUFFB + KOFF);
        const u64*    VPu = (const u64*)   (dsm + cur * BUFFB + VOFF);
        const float*  bias_s = (const float*)(dsm + cur * BUFFB + BOFF);

        /* ---- S = Q K^T (3-term fp16 k16), full 64-key tile ---- */
        float s[2][8][4];
        #pragma unroll
        for (int m = 0; m < 2; ++m)
            #pragma unroll
            for (int j = 0; j < 8; ++j)
                #pragma unroll
                for (int c = 0; c < 4; ++c) s[m][j][c] = 0.0f;
        #pragma unroll
        for (int ks = 0; ks < 2; ++ks) {
            #pragma unroll
            for (int j = 0; j < 8; ++j) {
                float4 kf = KP4[(4*ks + tq) * 66 + 8*j + g];
                u32 bh0 = __float_as_uint(kf.x), bh1 = __float_as_uint(kf.y);
                u32 bl0 = __float_as_uint(kf.z), bl1 = __float_as_uint(kf.w);
                #pragma unroll
                for (int m = 0; m < 2; ++m) {
                    MMA16(s[m][j], qh[m][ks], bh0, bh1);
                    MMA16(s[m][j], ql[m][ks], bh0, bh1);
                    MMA16(s[m][j], qh[m][ks], bl0, bl1);
                }
            }
        }

        /* ---- softmax over 64 keys ---- */
        float2 bb[8];
        #pragma unroll
        for (int j = 0; j < 8; ++j)
            bb[j] = *(const float2*)&bias_s[8*j + 2*tq];
        #pragma unroll
        for (int m = 0; m < 2; ++m)
            #pragma unroll
            for (int rg = 0; rg < 2; ++rg) {
                float zv[16];
                #pragma unroll
                for (int j = 0; j < 8; ++j) {
                    zv[2*j]   = fmaf(s[m][j][2*rg],   SCALE, bb[j].x);
                    zv[2*j+1] = fmaf(s[m][j][2*rg+1], SCALE, bb[j].y);
                }
                float m0 = fmaxf(zv[0], zv[1]),  m1 = fmaxf(zv[2], zv[3]);
                float m2 = fmaxf(zv[4], zv[5]),  m3 = fmaxf(zv[6], zv[7]);
                float m4 = fmaxf(zv[8], zv[9]),  m5 = fmaxf(zv[10], zv[11]);
                float m6 = fmaxf(zv[12], zv[13]), m7 = fmaxf(zv[14], zv[15]);
                float mx = fmaxf(fmaxf(fmaxf(m0, m1), fmaxf(m2, m3)),
                                 fmaxf(fmaxf(m4, m5), fmaxf(m6, m7)));
                mx = fmaxf(mx, __shfl_xor_sync(0xffffffffu, mx, 1));
                mx = fmaxf(mx, __shfl_xor_sync(0xffffffffu, mx, 2));
                float mn = fmaxf(mrun[m][rg], mx);
                float fr = __expf(mrun[m][rg] - mn);
                mrun[m][rg] = mn;
                float sum = 0.0f;
                #pragma unroll
                for (int j = 0; j < 8; ++j) {
                    float p0 = __expf(zv[2*j]   - mn);
                    float p1 = __expf(zv[2*j+1] - mn);
                    sum += p0 + p1;
                    s[m][j][2*rg] = p0; s[m][j][2*rg+1] = p1;
                }
                sum += __shfl_xor_sync(0xffffffffu, sum, 1);
                sum += __shfl_xor_sync(0xffffffffu, sum, 2);
                lrun[m][rg] = lrun[m][rg] * fr + sum;
                #pragma unroll
                for (int nf = 0; nf < 4; ++nf) {
                    O[m][nf][2*rg]   *= fr;
                    O[m][nf][2*rg+1] *= fr;
                }
            }
        /* drop key T-1 from ctx (still in softmax denom) */
        if (kt == T / 64 - 1 && tq == 3) {
            s[0][7][1] = 0.0f; s[0][7][3] = 0.0f;
            s[1][7][1] = 0.0f; s[1][7][3] = 0.0f;
        }

        /* ---- O += P V (2-term), P packed lane-locally (no smem) ---- */
        #pragma unroll
        for (int ks2 = 0; ks2 < 4; ++ks2) {
            u32 ph[2][4], pl[2][4];
            #pragma unroll
            for (int m = 0; m < 2; ++m) {
                f16split2(s[m][2*ks2][0],   s[m][2*ks2][1],   ph[m][0], pl[m][0]);
                f16split2(s[m][2*ks2][2],   s[m][2*ks2][3],   ph[m][1], pl[m][1]);
                f16split2(s[m][2*ks2+1][0], s[m][2*ks2+1][1], ph[m][2], pl[m][2]);
                f16split2(s[m][2*ks2+1][2], s[m][2*ks2+1][3], ph[m][3], pl[m][3]);
            }
            #pragma unroll
            for (int nf = 0; nf < 4; ++nf) {
                u64 vv = VPu[(4*ks2 + tq) * 36 + 8*nf + g];
                u32 v0 = (u32)vv, v1 = (u32)(vv >> 32);
                #pragma unroll
                for (int m = 0; m < 2; ++m) {
                    MMA16(O[m][nf], ph[m], v0, v1);
                    MMA16(O[m][nf], pl[m], v0, v1);
                }
            }
        }
        __syncthreads();
    }

    /* ---- epilogue ---- */
    #pragma unroll
    for (int m = 0; m < 2; ++m)
        #pragma unroll
        for (int rg = 0; rg < 2; ++rg) {
            int row = q0 + 32 * w + 16 * m + 8 * rg + g;
            float inv = g_qmask[nn * T + row] / lrun[m][rg];
            float* dst = &g_ctx[(size_t)(nn * T + row) * H + hh * D];
            #pragma unroll
            for (int nf = 0; nf < 4; ++nf)
                *(float2*)&dst[8*nf + 2*tq] =
                    make_float2(O[m][nf][2*rg] * inv, O[m][nf][2*rg+1] * inv);
        }
}

/* ------------------------------------------------------------------ */
__global__ void __launch_bounds__(256) ln_kernel(
        const float* __restrict__ gamma, const float* __restrict__ beta,
        float* __restrict__ out, float* __restrict__ wout) {
    int row = blockIdx.x, t = threadIdx.x;
    float x = g_ctx[(size_t)row * H + t];
    __shared__ float rs[8], rq[8];
    float s = x, q = x * x;
    #pragma unroll
    for (int o = 16; o; o >>= 1) {
        s += __shfl_xor_sync(0xffffffffu, s, o);
        q += __shfl_xor_sync(0xffffffffu, q, o);
    }
    if ((t & 31) == 0) { rs[t >> 5] = s; rq[t >> 5] = q; }
    __syncthreads();
    float ts = 0.0f, tq = 0.0f;
    #pragma unroll
    for (int i = 0; i < 8; ++i) { ts += rs[i]; tq += rq[i]; }
    float mu = ts * (1.0f / H);
    float var = tq * (1.0f / H) - mu * mu;
    float inv = rsqrtf(var + 1e-5f);
    out[(size_t)row * H + t] = (x - mu) * inv * gamma[t] + beta[t];
    if (t == 0) wout[row] = g_qmask[row] * (1.0f / (float)T);
}

/* ------------------------------------------------------------------ */
extern "C" void kernel_launch(void* const* d_in, const int* in_sizes, int n_in,
                              void* d_out, int out_size) {
    const float* Q  = (const float*)d_in[0];
    const float* K  = (const float*)d_in[1];
    const float* V  = (const float*)d_in[2];
    const float* Wq = (const float*)d_in[3];
    const float* bq = (const float*)d_in[4];
    const float* Wk = (const float*)d_in[5];
    const float* bk = (const float*)d_in[6];
    const float* Wv = (const float*)d_in[7];
    const float* bv = (const float*)d_in[8];
    const float* gamma = (const float*)d_in[9];
    const float* beta  = (const float*)d_in[10];

    float* out  = (float*)d_out;
    float* wout = out + (out_size - Nb * T);

    cudaFuncSetAttribute(attn_kernel,
                         cudaFuncAttributeMaxDynamicSharedMemorySize, SMEM_BYTES);

    mask_kernel<<<dim3(Nb * T, 2), 128>>>(Q, K);
    proj_kernel<<<dim3(H / 64, (Nb * T) / 64, 3), 256>>>(Q, K, V,
                                                         Wq, Wk, Wv,
                                                         bq, bk, bv);
    attn_kernel<<<dim3(T / 128, NH, Nb), 128, SMEM_BYTES>>>();
    ln_kernel<<<Nb * T, 256>>>(gamma, beta, out, wout);
}